// round 11
// baseline (speedup 1.0000x reference)
#include <cuda_runtime.h>
#include <cuda_bf16.h>
#include <cstdint>

#define NB 32
#define ND 64
#define NT 4096
#define NK 1024
#define NTOK (NB*NT)          // 131072 tokens
#define OUTQ (NB*ND*NT)       // 8388608 quantized elements

#define TCHUNKS 4             // tensor: codes 0..511 (bf16 3-product HMMA)
#define FBASE 512             // fma:    codes 512..1023 (exact fp32 f32x2)

#define CBSTRIDE 136          // ushorts per code row: [H(64)|M(64)|pad(8)] = 272B
#define CHUNK_CODES 128
#define TCHUNK_BYTES (CHUNK_CODES*CBSTRIDE*2)   // 34816
#define TCHUNK_16B (TCHUNK_BYTES/16)            // 2176
#define FCHUNK_BYTES (CHUNK_CODES*ND*4)         // 32768
#define FCHUNK_16B (FCHUNK_BYTES/16)            // 2048

#define SX_STRIDE 68          // floats per dim row (conflict-free)
#define SMEM_SX_BYTES (64*SX_STRIDE*4)          // 17408
#define SMEM_TCB 17408        // tensor chunk buffer (single)
#define SMEM_FCB 52224        // fma chunk buffer (single, fp32)
#define SMEM_TOTAL 84992      // fits 2 CTAs/SM (<=113664 each)

#define TAU 1e-3f
#define GT_TPB 256
#define NPART 2048            // gather blocks (64 tokens each)

// Scratch (no allocations allowed)
__device__ int            g_idx[NTOK];
__device__ float          g_part[NPART];
__device__ unsigned short g_cb[FBASE * CBSTRIDE];   // bf16 [H|M] rows, codes 0..511

// ============================ helpers ============================
static __device__ __forceinline__ uint32_t smem_to_u32(const void* p) {
    uint32_t a;
    asm("{ .reg .u64 tmp; cvta.to.shared.u64 tmp, %1; cvt.u32.u64 %0, tmp; }" : "=r"(a) : "l"(p));
    return a;
}
static __device__ __forceinline__ void cp_async16(uint32_t dst, const void* src) {
    asm volatile("cp.async.cg.shared.global [%0], [%1], 16;" :: "r"(dst), "l"(src) : "memory");
}
static __device__ __forceinline__ void cp_commit() {
    asm volatile("cp.async.commit_group;" ::: "memory");
}
static __device__ __forceinline__ void cp_wait0() {
    asm volatile("cp.async.wait_group 0;" ::: "memory");
}
static __device__ __forceinline__ void ldmatrix_x4(uint32_t& r0, uint32_t& r1,
                                                   uint32_t& r2, uint32_t& r3, uint32_t a) {
    asm volatile("ldmatrix.sync.aligned.m8n8.x4.shared.b16 {%0,%1,%2,%3}, [%4];"
        : "=r"(r0), "=r"(r1), "=r"(r2), "=r"(r3) : "r"(a));
}
static __device__ __forceinline__ void mma_bf16(float* c,
                                                uint32_t a0, uint32_t a1, uint32_t a2, uint32_t a3,
                                                uint32_t b0, uint32_t b1) {
    asm volatile("mma.sync.aligned.m16n8k16.row.col.f32.bf16.bf16.f32 "
        "{%0,%1,%2,%3}, {%4,%5,%6,%7}, {%8,%9}, {%0,%1,%2,%3};"
        : "+f"(c[0]), "+f"(c[1]), "+f"(c[2]), "+f"(c[3])
        : "r"(a0), "r"(a1), "r"(a2), "r"(a3), "r"(b0), "r"(b1));
}
static __device__ __forceinline__ uint32_t packbf(__nv_bfloat16 a, __nv_bfloat16 b) {
    return (uint32_t)__bfloat16_as_ushort(a) | ((uint32_t)__bfloat16_as_ushort(b) << 16);
}
static __device__ __forceinline__ unsigned long long pack2(float lo, float hi) {
    unsigned long long r;
    asm("mov.b64 %0, {%1, %2};" : "=l"(r) : "f"(lo), "f"(hi));
    return r;
}
static __device__ __forceinline__ float2 unpack2(unsigned long long v) {
    float2 f;
    asm("mov.b64 {%0, %1}, %2;" : "=f"(f.x), "=f"(f.y) : "l"(v));
    return f;
}
static __device__ __forceinline__ void ffma2(unsigned long long &acc,
                                             unsigned long long a, unsigned long long b) {
    asm("fma.rn.f32x2 %0, %1, %2, %3;" : "=l"(acc) : "l"(a), "l"(b), "l"(acc));
}
static __device__ __forceinline__ unsigned long long fadd2(unsigned long long a,
                                                           unsigned long long b) {
    unsigned long long r;
    asm("add.rn.f32x2 %0, %1, %2;" : "=l"(r) : "l"(a), "l"(b));
    return r;
}
// running top-2 update (ascending idx scan; first-max semantics)
static __device__ __forceinline__ void upd(float v, int idx, float& b, int& bi,
                                           float& s, int& si) {
    if (v > s) {
        if (v > b) { s = b; si = bi; b = v; bi = idx; }
        else       { s = v; si = idx; }
    }
}
// merge another top-2 into mine ((value desc, idx asc) priority)
static __device__ __forceinline__ void mrg2(float& b, int& bi, float& s, int& si,
                                            float ob, int obi, float os, int osi) {
    if (ob > b || (ob == b && obi < bi)) {
        if (b > os || (b == os && bi < osi)) { s = b;  si = bi; }
        else                                 { s = os; si = osi; }
        b = ob; bi = obi;
    } else if (ob > s || (ob == s && obi < si)) {
        s = ob; si = obi;
    }
}

// ---------------------------------------------------------------------------
// Kernel 0: split codebook rows (codes 0..511) into [H | M] bf16, padded.
// ---------------------------------------------------------------------------
__global__ void vq_prep_kernel(const float* __restrict__ emb)
{
    int i = blockIdx.x * blockDim.x + threadIdx.x;
    if (i >= FBASE * ND) return;
    int code = i >> 6, d = i & 63;
    float v = emb[i];
    __nv_bfloat16 h = __float2bfloat16_rn(v);
    __nv_bfloat16 m = __float2bfloat16_rn(v - __bfloat162float(h));
    g_cb[code * CBSTRIDE + d]      = __bfloat16_as_ushort(h);
    g_cb[code * CBSTRIDE + 64 + d] = __bfloat16_as_ushort(m);
}

// ---------------------------------------------------------------------------
// Kernel 1: in-warp hybrid argmax. CTA = 64 tokens (8 warps x 8 tokens).
// Codes 0..511:  bf16 3-product HMMA (hH+hM+mH, err<=~8e-5)  [tensor pipe]
// Codes 512..1023: exact fp32 f32x2, 16-code stretch after EVERY tensor tile
//                  (32 tiles x 16 = 512)                      [fma pipe]
// The HMMA completes async via scoreboard, so the FFMA2 stretch issues into
// the tensor pipe's rt=37 slack -> both pipes busy from the same warp.
// Near-ties (margin < TAU) -> warp-cooperative exact fp32 full rescan.
// ---------------------------------------------------------------------------
__global__ void __launch_bounds__(256, 2) vq_mma_argmax_kernel(
        const float* __restrict__ in, const float* __restrict__ emb,
        float* __restrict__ out)
{
    extern __shared__ float sx[];          // [64 dims][SX_STRIDE] fp32, then bufs
    const uint32_t sbase = smem_to_u32(sx);
    const int tid  = threadIdx.x;
    const int lane = tid & 31;
    const int w    = tid >> 5;
    const int gid  = lane >> 2;
    const int tig  = lane & 3;

    const int n0 = blockIdx.x * 64;
    const int b  = n0 >> 12;
    const int t0 = n0 & (NT - 1);

    // kick off chunk-0 loads (tensor bf16 + fma fp32) immediately
    for (int i = tid; i < TCHUNK_16B; i += 256)
        cp_async16(sbase + SMEM_TCB + i * 16, (const char*)g_cb + i * 16);
    {
        const char* fsrc = (const char*)(emb + (size_t)FBASE * ND);
        for (int i = tid; i < FCHUNK_16B; i += 256)
            cp_async16(sbase + SMEM_FCB + i * 16, fsrc + i * 16);
    }
    cp_commit();

    // stage x tile [64 d][64 t] fp32, coalesced
    {
        const float4* src = reinterpret_cast<const float4*>(in + (size_t)b * ND * NT + t0);
#pragma unroll
        for (int k = 0; k < 4; k++) {
            int i = tid + k * 256;
            int d = i >> 4, q = i & 15;
            float4 v = src[(size_t)d * (NT / 4) + q];
            *reinterpret_cast<float4*>(sx + d * SX_STRIDE + q * 4) = v;
        }
    }
    __syncthreads();   // sx visible

    // tensor-side token fragments (B operand): token = w*8 + gid
    const int tok = w * 8 + gid;
    uint32_t bh[8], bm[8];
#pragma unroll
    for (int j = 0; j < 4; j++) {
        int d0 = j * 16 + 2 * tig;
        float v0 = sx[d0 * SX_STRIDE + tok];
        float v1 = sx[(d0 + 1) * SX_STRIDE + tok];
        float v2 = sx[(d0 + 8) * SX_STRIDE + tok];
        float v3 = sx[(d0 + 9) * SX_STRIDE + tok];
        __nv_bfloat16 h0 = __float2bfloat16_rn(v0), h1 = __float2bfloat16_rn(v1);
        __nv_bfloat16 h2 = __float2bfloat16_rn(v2), h3 = __float2bfloat16_rn(v3);
        bh[2*j]   = packbf(h0, h1);
        bh[2*j+1] = packbf(h2, h3);
        bm[2*j]   = packbf(__float2bfloat16_rn(v0 - __bfloat162float(h0)),
                           __float2bfloat16_rn(v1 - __bfloat162float(h1)));
        bm[2*j+1] = packbf(__float2bfloat16_rn(v2 - __bfloat162float(h2)),
                           __float2bfloat16_rn(v3 - __bfloat162float(h3)));
    }

    // fma-side x slice: token ftok = w*8 + (lane&7), dims [seg*16, seg*16+16)
    const int ftok = w * 8 + (lane & 7);
    const int seg  = lane >> 3;
    unsigned long long xpf[8];
#pragma unroll
    for (int j = 0; j < 8; j++)
        xpf[j] = pack2(sx[(seg * 16 + 2*j) * SX_STRIDE + ftok],
                       sx[(seg * 16 + 2*j + 1) * SX_STRIDE + ftok]);

    cp_wait0();
    __syncthreads();   // chunk 0 ready

    float bestv[2] = { -3.0e38f, -3.0e38f }, secv[2] = { -3.0e38f, -3.0e38f };
    int   besti[2] = { 0, 0 },               seci[2] = { 0, 0 };
    float fbest = -3.0e38f, fsec = -3.0e38f;
    int   fbi = 0, fsi = 0;

    const uint32_t lmoff = (uint32_t)((lane & 15) * (CBSTRIDE * 2) + ((lane >> 4) * 16));
    const char* fmabuf = reinterpret_cast<const char*>(sx) + SMEM_FCB;

    for (int c = 0; c < TCHUNKS; c++) {
#pragma unroll 1
        for (int mt = 0; mt < 8; mt++) {
            // ---- tensor tile: 16 codes, 12 HMMA, phase-split fragments ----
            uint32_t lm = sbase + SMEM_TCB + lmoff + (uint32_t)(mt * 16 * CBSTRIDE * 2);
            float p[4] = {0,0,0,0}, q[4] = {0,0,0,0}, r[4] = {0,0,0,0};
            {
                uint32_t AF[16];
#pragma unroll
                for (int jj = 0; jj < 4; jj++)
                    ldmatrix_x4(AF[4*jj], AF[4*jj+1], AF[4*jj+2], AF[4*jj+3], lm + jj * 32);
#pragma unroll
                for (int jj = 0; jj < 4; jj++) {
                    mma_bf16(p, AF[4*jj], AF[4*jj+1], AF[4*jj+2], AF[4*jj+3], bh[2*jj], bh[2*jj+1]);
                    mma_bf16(r, AF[4*jj], AF[4*jj+1], AF[4*jj+2], AF[4*jj+3], bm[2*jj], bm[2*jj+1]);
                }
#pragma unroll
                for (int jj = 0; jj < 4; jj++)
                    ldmatrix_x4(AF[4*jj], AF[4*jj+1], AF[4*jj+2], AF[4*jj+3], lm + 128 + jj * 32);
#pragma unroll
                for (int jj = 0; jj < 4; jj++)
                    mma_bf16(q, AF[4*jj], AF[4*jj+1], AF[4*jj+2], AF[4*jj+3], bh[2*jj], bh[2*jj+1]);
            }

            // ---- fma stretch: 16 exact fp32 codes (issues into HMMA slack) ----
            {
                const char* base = fmabuf + ((mt * 16) << 8) + (seg << 6);
                const int fb0 = FBASE + c * CHUNK_CODES + mt * 16;
#pragma unroll 4
                for (int k = 0; k < 16; k++) {
                    const ulonglong2* row =
                        reinterpret_cast<const ulonglong2*>(base + (k << 8));
                    ulonglong2 e0 = row[0], e1 = row[1], e2 = row[2], e3 = row[3];
                    unsigned long long a0 = 0ull, a1 = 0ull, a2 = 0ull, a3 = 0ull;
                    ffma2(a0, xpf[0], e0.x); ffma2(a1, xpf[1], e0.y);
                    ffma2(a2, xpf[2], e1.x); ffma2(a3, xpf[3], e1.y);
                    ffma2(a0, xpf[4], e2.x); ffma2(a1, xpf[5], e2.y);
                    ffma2(a2, xpf[6], e3.x); ffma2(a3, xpf[7], e3.y);
                    unsigned long long s2 = fadd2(fadd2(a0, a1), fadd2(a2, a3));
                    float2 f = unpack2(s2);
                    float v = f.x + f.y;
                    v += __shfl_xor_sync(0xffffffffu, v, 8);
                    v += __shfl_xor_sync(0xffffffffu, v, 16);
                    upd(v, fb0 + k, fbest, fbi, fsec, fsi);
                }
            }

            // ---- tensor epilogue ----
            const int ib = c * CHUNK_CODES + mt * 16;
            float f0 = p[0] + q[0] + r[0];
            float f1 = p[1] + q[1] + r[1];
            float f2 = p[2] + q[2] + r[2];
            float f3 = p[3] + q[3] + r[3];
            upd(f0, ib + gid,     bestv[0], besti[0], secv[0], seci[0]);
            upd(f1, ib + gid,     bestv[1], besti[1], secv[1], seci[1]);
            upd(f2, ib + gid + 8, bestv[0], besti[0], secv[0], seci[0]);
            upd(f3, ib + gid + 8, bestv[1], besti[1], secv[1], seci[1]);
        }

        if (c + 1 < TCHUNKS) {
            __syncthreads();   // everyone done reading both buffers
            const char* tsrc = (const char*)g_cb + (size_t)(c + 1) * TCHUNK_BYTES;
            for (int i = tid; i < TCHUNK_16B; i += 256)
                cp_async16(sbase + SMEM_TCB + i * 16, tsrc + i * 16);
            const char* fsrc = (const char*)(emb + (size_t)(FBASE + (c + 1) * CHUNK_CODES) * ND);
            for (int i = tid; i < FCHUNK_16B; i += 256)
                cp_async16(sbase + SMEM_FCB + i * 16, fsrc + i * 16);
            cp_commit();
            cp_wait0();
            __syncthreads();
        }
    }

    // butterfly merge of tensor top-2 across the 8 row-groups
#pragma unroll
    for (int off = 4; off <= 16; off <<= 1)
#pragma unroll
        for (int col = 0; col < 2; col++) {
            float ob  = __shfl_xor_sync(0xffffffffu, bestv[col], off);
            int   obi = __shfl_xor_sync(0xffffffffu, besti[col], off);
            float os  = __shfl_xor_sync(0xffffffffu, secv[col],  off);
            int   osi = __shfl_xor_sync(0xffffffffu, seci[col],  off);
            mrg2(bestv[col], besti[col], secv[col], seci[col], ob, obi, os, osi);
        }

    // merge fma top-2 (token k lives in lane k, 0..7): lane l<4 owns tokens 2l, 2l+1
#pragma unroll
    for (int col = 0; col < 2; col++) {
        int srcl = 2 * lane + col;   // lanes >=4 produce junk srcl; results unused there
        float ob  = __shfl_sync(0xffffffffu, fbest, srcl & 31);
        int   obi = __shfl_sync(0xffffffffu, fbi,   srcl & 31);
        float os  = __shfl_sync(0xffffffffu, fsec,  srcl & 31);
        int   osi = __shfl_sync(0xffffffffu, fsi,   srcl & 31);
        mrg2(bestv[col], besti[col], secv[col], seci[col], ob, obi, os, osi);
    }

    // near-tie rescue: full exact fp32 rescan of ALL 1024 codes
    unsigned m0 = __ballot_sync(0xffffffffu, (lane < 4) && (bestv[0] - secv[0] < TAU)) & 0xFu;
    unsigned m1 = __ballot_sync(0xffffffffu, (lane < 4) && (bestv[1] - secv[1] < TAU)) & 0xFu;
    if (m0 | m1) {
        for (int l = 0; l < 4; l++) {
#pragma unroll
            for (int col = 0; col < 2; col++) {
                unsigned mm = col ? m1 : m0;
                if ((mm >> l) & 1u) {
                    const int ts = w * 8 + 2 * l + col;   // token slot in block-tile
                    float bb = -3.0e38f; int bi = 0;
                    for (int cc = lane; cc < NK; cc += 32) {
                        const float* e = emb + (size_t)cc * ND;
                        float a0 = 0.f, a1 = 0.f, a2 = 0.f, a3 = 0.f;
#pragma unroll
                        for (int d = 0; d < ND; d += 4) {
                            a0 = fmaf(sx[d * SX_STRIDE + ts],       e[d],     a0);
                            a1 = fmaf(sx[(d + 1) * SX_STRIDE + ts], e[d + 1], a1);
                            a2 = fmaf(sx[(d + 2) * SX_STRIDE + ts], e[d + 2], a2);
                            a3 = fmaf(sx[(d + 3) * SX_STRIDE + ts], e[d + 3], a3);
                        }
                        float v = (a0 + a1) + (a2 + a3);
                        if (v > bb) { bb = v; bi = cc; }
                    }
#pragma unroll
                    for (int off = 16; off; off >>= 1) {
                        float ov = __shfl_xor_sync(0xffffffffu, bb, off);
                        int   oi = __shfl_xor_sync(0xffffffffu, bi, off);
                        if (ov > bb || (ov == bb && oi < bi)) { bb = ov; bi = oi; }
                    }
                    if (lane == l) besti[col] = bi;
                }
            }
        }
    }

    if (lane < 4) {
        const int n = n0 + w * 8 + 2 * lane;
        g_idx[n]     = besti[0];
        g_idx[n + 1] = besti[1];
        out[OUTQ + 2 + n]     = (float)besti[0];
        out[OUTQ + 2 + n + 1] = (float)besti[1];
    }
}

// ---------------------------------------------------------------------------
// Kernel 2: gather quantized output + loss partials (coalesced, smem-staged).
// commitment_loss == codebook_loss forward == mean((flat - emb_unnorm[idx])^2)
// ---------------------------------------------------------------------------
__global__ void __launch_bounds__(GT_TPB) vq_gather_loss_kernel(
        const float* __restrict__ in, const float* __restrict__ emb,
        const float* __restrict__ embu, float* __restrict__ out)
{
    __shared__ int   sidx[64];
    __shared__ float sq[64 * 65];
    __shared__ float su[64 * 65];

    const int tid = threadIdx.x;
    const int n0  = blockIdx.x * 64;
    const int b   = n0 >> 12;
    const int t0  = n0 & (NT - 1);

    if (tid < 64) sidx[tid] = g_idx[n0 + tid];
    __syncthreads();

    {
        const int tok = tid >> 2;
        const int q   = tid & 3;
        const int code = sidx[tok];
        const float4* e4 = reinterpret_cast<const float4*>(emb  + (size_t)code * ND);
        const float4* u4 = reinterpret_cast<const float4*>(embu + (size_t)code * ND);
#pragma unroll
        for (int j = 0; j < 4; j++) {
            float4 f = e4[q * 4 + j];
            float4 u = u4[q * 4 + j];
            int base = tok * 65 + q * 16 + j * 4;
            sq[base] = f.x; sq[base+1] = f.y; sq[base+2] = f.z; sq[base+3] = f.w;
            su[base] = u.x; su[base+1] = u.y; su[base+2] = u.z; su[base+3] = u.w;
        }
    }
    __syncthreads();

    const int d  = tid >> 2;
    const int j0 = (tid & 3) * 16;
    const size_t gbase = (size_t)b * ND * NT + (size_t)d * NT + t0 + j0;
    float lsum = 0.f;
#pragma unroll
    for (int i = 0; i < 16; i++) {
        float xi = in[gbase + i];
        out[gbase + i] = sq[(j0 + i) * 65 + d];
        float df = xi - su[(j0 + i) * 65 + d];
        lsum += df * df;
    }

#pragma unroll
    for (int o = 16; o; o >>= 1) lsum += __shfl_xor_sync(0xffffffffu, lsum, o);
    __shared__ float ws[GT_TPB / 32];
    if ((tid & 31) == 0) ws[tid >> 5] = lsum;
    __syncthreads();
    if (tid < 32) {
        float v = (tid < GT_TPB / 32) ? ws[tid] : 0.f;
#pragma unroll
        for (int o = 4; o; o >>= 1) v += __shfl_xor_sync(0xffffffffu, v, o);
        if (tid == 0) g_part[blockIdx.x] = v;
    }
}

// ---------------------------------------------------------------------------
// Kernel 3: final loss reduction (double precision), write scalars.
// ---------------------------------------------------------------------------
__global__ void vq_finalize_kernel(float* __restrict__ out)
{
    __shared__ double sd[256];
    double s = 0.0;
    for (int i = threadIdx.x; i < NPART; i += 256) s += (double)g_part[i];
    sd[threadIdx.x] = s;
    __syncthreads();
    for (int o = 128; o; o >>= 1) {
        if (threadIdx.x < o) sd[threadIdx.x] += sd[threadIdx.x + o];
        __syncthreads();
    }
    if (threadIdx.x == 0) {
        float m = (float)(sd[0] / (double)OUTQ);
        out[OUTQ]     = m;   // commitment_loss
        out[OUTQ + 1] = m;   // codebook_loss (numerically identical forward)
    }
}

extern "C" void kernel_launch(void* const* d_in, const int* in_sizes, int n_in,
                              void* d_out, int out_size) {
    const float* in   = (const float*)d_in[0];   // [32, 64, 4096] fp32
    const float* emb  = (const float*)d_in[1];   // [1024, 64] fp32 (pre-normalized)
    const float* embu = (const float*)d_in[2];   // [1024, 64] fp32
    float* out = (float*)d_out;

    static int configured = 0;
    if (!configured) {
        cudaFuncSetAttribute(vq_mma_argmax_kernel,
                             cudaFuncAttributeMaxDynamicSharedMemorySize, SMEM_TOTAL);
        configured = 1;
    }

    vq_prep_kernel<<<(FBASE * ND) / 256, 256>>>(emb);
    vq_mma_argmax_kernel<<<NTOK / 64, 256, SMEM_TOTAL>>>(in, emb, out);
    vq_gather_loss_kernel<<<NPART, GT_TPB>>>(in, emb, embu, out);
    vq_finalize_kernel<<<1, 256>>>(out);
}

// round 12
// speedup vs baseline: 1.6811x; 1.6811x over previous
#include <cuda_runtime.h>
#include <cuda_bf16.h>
#include <cstdint>

#define NB 32
#define ND 64
#define NT 4096
#define NK 1024
#define NTOK (NB*NT)          // 131072 tokens
#define OUTQ (NB*ND*NT)       // 8388608 quantized elements

#define CBSTRIDE 136          // ushorts per code row: [H(64) | M(64) | pad(8)] = 272B
#define CHUNK_CODES 128
#define NCHUNK (NK/CHUNK_CODES)       // 8
#define CHUNK_BYTES (CHUNK_CODES*CBSTRIDE*2)   // 34816
#define CHUNK_16B (CHUNK_BYTES/16)             // 2176

#define SX_STRIDE 68          // floats per dim row (conflict-free)
#define SMEM_SX_BYTES (64*SX_STRIDE*4)         // 17408
#define SMEM_CB0 SMEM_SX_BYTES                 // 17408
#define SMEM_CB1 (SMEM_CB0 + CHUNK_BYTES)      // 52224
#define SMEM_TOTAL (SMEM_CB1 + CHUNK_BYTES)    // 87040
// post-mainloop overlays (chunk buffers are dead then):
//   sidx: SMEM_CB0          (256 B)
//   sq  : SMEM_CB0 + 1024   (64*65*4 = 16640 B, fits in CB0's 34816)
//   su  : SMEM_CB1          (16640 B, fits in CB1's 34816)

#define TAU 1e-3f
#define NPART (NTOK/64)       // 2048 argmax CTAs, one loss partial each

// Scratch (no allocations allowed)
__device__ float          g_part[NPART];
__device__ unsigned short g_cb[NK * CBSTRIDE];   // codebook split [H|M] bf16, padded rows

// ============================ helpers ============================
static __device__ __forceinline__ uint32_t smem_to_u32(const void* p) {
    uint32_t a;
    asm("{ .reg .u64 tmp; cvta.to.shared.u64 tmp, %1; cvt.u32.u64 %0, tmp; }" : "=r"(a) : "l"(p));
    return a;
}
static __device__ __forceinline__ void cp_async16(uint32_t dst, const void* src) {
    asm volatile("cp.async.cg.shared.global [%0], [%1], 16;" :: "r"(dst), "l"(src) : "memory");
}
static __device__ __forceinline__ void cp_commit() {
    asm volatile("cp.async.commit_group;" ::: "memory");
}
static __device__ __forceinline__ void cp_wait1() {
    asm volatile("cp.async.wait_group 1;" ::: "memory");
}
static __device__ __forceinline__ void cp_wait0() {
    asm volatile("cp.async.wait_group 0;" ::: "memory");
}
static __device__ __forceinline__ void ldmatrix_x4(uint32_t& r0, uint32_t& r1,
                                                   uint32_t& r2, uint32_t& r3, uint32_t a) {
    asm volatile("ldmatrix.sync.aligned.m8n8.x4.shared.b16 {%0,%1,%2,%3}, [%4];"
        : "=r"(r0), "=r"(r1), "=r"(r2), "=r"(r3) : "r"(a));
}
static __device__ __forceinline__ void mma_bf16(float* c,
                                                uint32_t a0, uint32_t a1, uint32_t a2, uint32_t a3,
                                                uint32_t b0, uint32_t b1) {
    asm volatile("mma.sync.aligned.m16n8k16.row.col.f32.bf16.bf16.f32 "
        "{%0,%1,%2,%3}, {%4,%5,%6,%7}, {%8,%9}, {%0,%1,%2,%3};"
        : "+f"(c[0]), "+f"(c[1]), "+f"(c[2]), "+f"(c[3])
        : "r"(a0), "r"(a1), "r"(a2), "r"(a3), "r"(b0), "r"(b1));
}
static __device__ __forceinline__ uint32_t packbf(__nv_bfloat16 a, __nv_bfloat16 b) {
    return (uint32_t)__bfloat16_as_ushort(a) | ((uint32_t)__bfloat16_as_ushort(b) << 16);
}
// running top-2 update (ascending idx scan; first-max semantics)
static __device__ __forceinline__ void upd(float v, int idx, float& b, int& bi,
                                           float& s, int& si) {
    if (v > s) {
        if (v > b) { s = b; si = bi; b = v; bi = idx; }
        else       { s = v; si = idx; }
    }
}
// merge another top-2 into mine ((value desc, idx asc) priority)
static __device__ __forceinline__ void mrg(float& b, int& bi, float& s, int& si,
                                           float ob, int obi, float os, int osi) {
    if (ob > b || (ob == b && obi < bi)) {
        if (b > os || (b == os && bi < osi)) { s = b;  si = bi; }
        else                                 { s = os; si = osi; }
        b = ob; bi = obi;
    } else if (ob > s || (ob == s && obi < si)) {
        s = ob; si = obi;
    }
}

// ---------------------------------------------------------------------------
// Kernel 0: split codebook rows into [H | M] bf16, padded stride.
// H = bf16(v); M = bf16(v - H).
// ---------------------------------------------------------------------------
__global__ void vq_prep_kernel(const float* __restrict__ emb)
{
    int i = blockIdx.x * blockDim.x + threadIdx.x;
    if (i >= NK * ND) return;
    int code = i >> 6, d = i & 63;
    float v = emb[i];
    __nv_bfloat16 h = __float2bfloat16_rn(v);
    float r = v - __bfloat162float(h);
    __nv_bfloat16 m = __float2bfloat16_rn(r);
    g_cb[code * CBSTRIDE + d]      = __bfloat16_as_ushort(h);
    g_cb[code * CBSTRIDE + 64 + d] = __bfloat16_as_ushort(m);
}

// ---------------------------------------------------------------------------
// Kernel 1: mma.sync bf16 argmax + FUSED gather/loss tail.
// CTA = 64 tokens (8 warps x 8 tokens). Core is the proven R4 pipeline:
// scores = x.e via hH + hM + mH (err ~1e-5); top-2 tracked; near-ties
// (margin < TAU) -> warp-cooperative exact fp32 rescan of all codes.
// Tail: the CTA already holds its x tile in smem (sx), so it directly
// gathers emb/embu rows (staged via the now-dead chunk buffers), writes the
// quantized [d][t] tile coalesced, and emits its loss partial. This removes
// the separate gather kernel and its 33.5 MB re-read of `in`.
// ---------------------------------------------------------------------------
__global__ void __launch_bounds__(256, 2) vq_mma_argmax_kernel(
        const float* __restrict__ in, const float* __restrict__ emb,
        const float* __restrict__ embu, float* __restrict__ out)
{
    extern __shared__ float sx[];          // [64 dims][SX_STRIDE] fp32, then code bufs
    const uint32_t sbase = smem_to_u32(sx);
    char* smemc = reinterpret_cast<char*>(sx);
    const int tid  = threadIdx.x;
    const int lane = tid & 31;
    const int w    = tid >> 5;
    const int gid  = lane >> 2;
    const int tig  = lane & 3;

    const int n0 = blockIdx.x * 64;
    const int b  = n0 >> 12;
    const int t0 = n0 & (NT - 1);

    // stage x tile [64 d][64 t] fp32, coalesced
    {
        const float4* src = reinterpret_cast<const float4*>(in + (size_t)b * ND * NT + t0);
#pragma unroll
        for (int k = 0; k < 4; k++) {
            int i = tid + k * 256;
            int d = i >> 4, q = i & 15;
            float4 v = src[(size_t)d * (NT / 4) + q];
            *reinterpret_cast<float4*>(sx + d * SX_STRIDE + q * 4) = v;
        }
    }
    // preload code chunk 0
    for (int i = tid; i < CHUNK_16B; i += 256)
        cp_async16(sbase + SMEM_CB0 + i * 16, (const char*)g_cb + i * 16);
    cp_commit();
    __syncthreads();   // sx visible

    // build token-side fragments (B operand): token = w*8 + gid
    const int tok = w * 8 + gid;
    uint32_t bh[8], bm[8];
#pragma unroll
    for (int j = 0; j < 4; j++) {
        int d0 = j * 16 + 2 * tig;
        float v0 = sx[d0 * SX_STRIDE + tok];
        float v1 = sx[(d0 + 1) * SX_STRIDE + tok];
        float v2 = sx[(d0 + 8) * SX_STRIDE + tok];
        float v3 = sx[(d0 + 9) * SX_STRIDE + tok];
        __nv_bfloat16 h0 = __float2bfloat16_rn(v0), h1 = __float2bfloat16_rn(v1);
        __nv_bfloat16 h2 = __float2bfloat16_rn(v2), h3 = __float2bfloat16_rn(v3);
        bh[2*j]   = packbf(h0, h1);
        bh[2*j+1] = packbf(h2, h3);
        bm[2*j]   = packbf(__float2bfloat16_rn(v0 - __bfloat162float(h0)),
                           __float2bfloat16_rn(v1 - __bfloat162float(h1)));
        bm[2*j+1] = packbf(__float2bfloat16_rn(v2 - __bfloat162float(h2)),
                           __float2bfloat16_rn(v3 - __bfloat162float(h3)));
    }

    float bestv[2] = { -3.0e38f, -3.0e38f }, secv[2] = { -3.0e38f, -3.0e38f };
    int   besti[2] = { 0, 0 },               seci[2] = { 0, 0 };

    const uint32_t lmbase = sbase + (uint32_t)((lane & 15) * (CBSTRIDE * 2) + ((lane >> 4) * 16));

    for (int c = 0; c < NCHUNK; c++) {
        const uint32_t bufo = (c & 1) ? SMEM_CB1 : SMEM_CB0;
        if (c + 1 < NCHUNK) {
            const uint32_t nbufo = (c & 1) ? SMEM_CB0 : SMEM_CB1;
            const char* src = (const char*)g_cb + (size_t)(c + 1) * CHUNK_BYTES;
            for (int i = tid; i < CHUNK_16B; i += 256)
                cp_async16(sbase + nbufo + i * 16, src + i * 16);
            cp_commit();
            cp_wait1();
        } else {
            cp_wait0();
        }
        __syncthreads();

#pragma unroll 2
        for (int mt = 0; mt < 8; mt++) {
            uint32_t lm = lmbase + bufo + (uint32_t)(mt * 16 * CBSTRIDE * 2);
            uint32_t AH[16], AM[16];
#pragma unroll
            for (int jj = 0; jj < 4; jj++) {
                ldmatrix_x4(AH[4*jj], AH[4*jj+1], AH[4*jj+2], AH[4*jj+3], lm + jj * 32);
                ldmatrix_x4(AM[4*jj], AM[4*jj+1], AM[4*jj+2], AM[4*jj+3], lm + 128 + jj * 32);
            }
            float p[4] = {0,0,0,0}, q[4] = {0,0,0,0}, r[4] = {0,0,0,0};
#pragma unroll
            for (int jj = 0; jj < 4; jj++) {
                mma_bf16(p, AH[4*jj], AH[4*jj+1], AH[4*jj+2], AH[4*jj+3], bh[2*jj], bh[2*jj+1]);
                mma_bf16(q, AM[4*jj], AM[4*jj+1], AM[4*jj+2], AM[4*jj+3], bh[2*jj], bh[2*jj+1]);
                mma_bf16(r, AH[4*jj], AH[4*jj+1], AH[4*jj+2], AH[4*jj+3], bm[2*jj], bm[2*jj+1]);
            }
            const int ib = c * CHUNK_CODES + mt * 16;
            float f0 = p[0] + q[0] + r[0];
            float f1 = p[1] + q[1] + r[1];
            float f2 = p[2] + q[2] + r[2];
            float f3 = p[3] + q[3] + r[3];
            upd(f0, ib + gid,     bestv[0], besti[0], secv[0], seci[0]);
            upd(f1, ib + gid,     bestv[1], besti[1], secv[1], seci[1]);
            upd(f2, ib + gid + 8, bestv[0], besti[0], secv[0], seci[0]);
            upd(f3, ib + gid + 8, bestv[1], besti[1], secv[1], seci[1]);
        }
        __syncthreads();
    }

    // butterfly merge of top-2 across the 8 row-groups (lanes differing in bits 2..4)
#pragma unroll
    for (int off = 4; off <= 16; off <<= 1) {
#pragma unroll
        for (int col = 0; col < 2; col++) {
            float ob  = __shfl_xor_sync(0xffffffffu, bestv[col], off);
            int   obi = __shfl_xor_sync(0xffffffffu, besti[col], off);
            float os  = __shfl_xor_sync(0xffffffffu, secv[col],  off);
            int   osi = __shfl_xor_sync(0xffffffffu, seci[col],  off);
            mrg(bestv[col], besti[col], secv[col], seci[col], ob, obi, os, osi);
        }
    }

    // near-tie rescue: full exact fp32 rescan, warp-cooperative (uniform control)
    unsigned m0 = __ballot_sync(0xffffffffu, (lane < 4) && (bestv[0] - secv[0] < TAU)) & 0xFu;
    unsigned m1 = __ballot_sync(0xffffffffu, (lane < 4) && (bestv[1] - secv[1] < TAU)) & 0xFu;
    if (m0 | m1) {
        for (int l = 0; l < 4; l++) {
#pragma unroll
            for (int col = 0; col < 2; col++) {
                unsigned mm = col ? m1 : m0;
                if ((mm >> l) & 1u) {
                    const int ts = w * 8 + 2 * l + col;   // token slot in block-tile
                    float bb = -3.0e38f; int bi = 0;
                    for (int cc = lane; cc < NK; cc += 32) {
                        const float* e = emb + (size_t)cc * ND;
                        float a0 = 0.f, a1 = 0.f, a2 = 0.f, a3 = 0.f;
#pragma unroll
                        for (int d = 0; d < ND; d += 4) {
                            a0 = fmaf(sx[d * SX_STRIDE + ts],       e[d],     a0);
                            a1 = fmaf(sx[(d + 1) * SX_STRIDE + ts], e[d + 1], a1);
                            a2 = fmaf(sx[(d + 2) * SX_STRIDE + ts], e[d + 2], a2);
                            a3 = fmaf(sx[(d + 3) * SX_STRIDE + ts], e[d + 3], a3);
                        }
                        float v = (a0 + a1) + (a2 + a3);
                        if (v > bb) { bb = v; bi = cc; }
                    }
#pragma unroll
                    for (int off = 16; off; off >>= 1) {
                        float ov = __shfl_xor_sync(0xffffffffu, bb, off);
                        int   oi = __shfl_xor_sync(0xffffffffu, bi, off);
                        if (ov > bb || (ov == bb && oi < bi)) { bb = ov; bi = oi; }
                    }
                    if (lane == l) besti[col] = bi;
                }
            }
        }
    }

    // ============ FUSED TAIL: idx write + gather + loss partial ============
    // overlay the dead chunk buffers
    int*   sidx = reinterpret_cast<int*>(smemc + SMEM_CB0);
    float* sq   = reinterpret_cast<float*>(smemc + SMEM_CB0 + 1024);
    float* su   = reinterpret_cast<float*>(smemc + SMEM_CB1);

    __syncthreads();   // everyone done with chunk buffers & rescue reads of sx
    if (lane < 4) {
        const int tk = w * 8 + 2 * lane;
        const int n  = n0 + tk;
        sidx[tk]     = besti[0];
        sidx[tk + 1] = besti[1];
        out[OUTQ + 2 + n]     = (float)besti[0];
        out[OUTQ + 2 + n + 1] = (float)besti[1];
    }
    __syncthreads();

    // gather emb/embu rows, coalesced on codebook rows (4 threads per token)
    {
        const int gtok = tid >> 2;
        const int qq   = tid & 3;
        const int code = sidx[gtok];
        const float4* e4 = reinterpret_cast<const float4*>(emb  + (size_t)code * ND);
        const float4* u4 = reinterpret_cast<const float4*>(embu + (size_t)code * ND);
#pragma unroll
        for (int j = 0; j < 4; j++) {
            float4 f = e4[qq * 4 + j];
            float4 u = u4[qq * 4 + j];
            int base = gtok * 65 + qq * 16 + j * 4;
            sq[base] = f.x; sq[base+1] = f.y; sq[base+2] = f.z; sq[base+3] = f.w;
            su[base] = u.x; su[base+1] = u.y; su[base+2] = u.z; su[base+3] = u.w;
        }
    }
    __syncthreads();

    // write [64 d x 64 t] quantized tile coalesced; loss from sx (no in re-read)
    {
        const int d  = tid >> 2;
        const int j0 = (tid & 3) * 16;
        const size_t gbase = (size_t)b * ND * NT + (size_t)d * NT + t0 + j0;
        float lsum = 0.f;
#pragma unroll
        for (int i = 0; i < 16; i++) {
            float xi = sx[d * SX_STRIDE + j0 + i];
            out[gbase + i] = sq[(j0 + i) * 65 + d];
            float df = xi - su[(j0 + i) * 65 + d];
            lsum += df * df;
        }
#pragma unroll
        for (int o = 16; o; o >>= 1) lsum += __shfl_xor_sync(0xffffffffu, lsum, o);
        // reuse sidx region (done) as a tiny reduce buffer
        float* ws = reinterpret_cast<float*>(smemc + SMEM_CB1 + 17408);
        if ((tid & 31) == 0) ws[tid >> 5] = lsum;
        __syncthreads();
        if (tid < 32) {
            float v = (tid < 8) ? ws[tid] : 0.f;
#pragma unroll
            for (int o = 4; o; o >>= 1) v += __shfl_xor_sync(0xffffffffu, v, o);
            if (tid == 0) g_part[blockIdx.x] = v;
        }
    }
}

// ---------------------------------------------------------------------------
// Kernel 2: final loss reduction (double precision), write scalars.
// commitment_loss == codebook_loss forward == mean((flat - emb_unnorm[idx])^2)
// ---------------------------------------------------------------------------
__global__ void vq_finalize_kernel(float* __restrict__ out)
{
    __shared__ double sd[256];
    double s = 0.0;
    for (int i = threadIdx.x; i < NPART; i += 256) s += (double)g_part[i];
    sd[threadIdx.x] = s;
    __syncthreads();
    for (int o = 128; o; o >>= 1) {
        if (threadIdx.x < o) sd[threadIdx.x] += sd[threadIdx.x + o];
        __syncthreads();
    }
    if (threadIdx.x == 0) {
        float m = (float)(sd[0] / (double)OUTQ);
        out[OUTQ]     = m;   // commitment_loss
        out[OUTQ + 1] = m;   // codebook_loss (numerically identical forward)
    }
}

extern "C" void kernel_launch(void* const* d_in, const int* in_sizes, int n_in,
                              void* d_out, int out_size) {
    const float* in   = (const float*)d_in[0];   // [32, 64, 4096] fp32
    const float* emb  = (const float*)d_in[1];   // [1024, 64] fp32 (pre-normalized)
    const float* embu = (const float*)d_in[2];   // [1024, 64] fp32
    float* out = (float*)d_out;

    static int configured = 0;
    if (!configured) {
        cudaFuncSetAttribute(vq_mma_argmax_kernel,
                             cudaFuncAttributeMaxDynamicSharedMemorySize, SMEM_TOTAL);
        configured = 1;
    }

    vq_prep_kernel<<<(NK * ND) / 256, 256>>>(emb);
    vq_mma_argmax_kernel<<<NTOK / 64, 256, SMEM_TOTAL>>>(in, emb, embu, out);
    vq_finalize_kernel<<<1, 256>>>(out);
}

// round 13
// speedup vs baseline: 2.2489x; 1.3377x over previous
#include <cuda_runtime.h>
#include <cuda_fp16.h>
#include <cstdint>

#define NB 32
#define ND 64
#define NT 4096
#define NK 1024
#define NTOK (NB*NT)          // 131072 tokens
#define OUTQ (NB*ND*NT)       // 8388608 quantized elements

#define CBROW 144             // bytes per code row: [H(64 fp16) | pad(16)]
#define CHUNK_CODES 128
#define NCHUNK (NK/CHUNK_CODES)                // 8
#define CHUNK_BYTES (CHUNK_CODES*CBROW)        // 18432
#define CHUNK_16B (CHUNK_BYTES/16)             // 1152

#define SX_STRIDE 68          // floats per dim row (conflict-free)
#define SMEM_SX_BYTES (64*SX_STRIDE*4)         // 17408
#define SMEM_CB0 SMEM_SX_BYTES                 // 17408
#define SMEM_CB1 (SMEM_CB0 + CHUNK_BYTES)      // 35840
#define SMEM_TOTAL (SMEM_CB1 + CHUNK_BYTES)    // 54272
// post-mainloop overlays (chunk buffers dead):
//   sidx at SMEM_CB0 (256 B); sq at SMEM_CB0+1024 (16640 B);
//   su at SMEM_CB1 (16640 B); ws at SMEM_CB1+16640 (32 B)

#define WINC 1.15e-3f         // window = WINC * ||x|| (err bound 4.9e-4*||x||, x2, pad)
#define NPART (NTOK/64)       // 2048 argmax CTAs, one loss partial each

// Scratch (no allocations allowed)
__device__ float          g_part[NPART];
__device__ unsigned short g_cb[NK * (CBROW/2)];   // fp16 codebook, padded rows

// ============================ helpers ============================
static __device__ __forceinline__ uint32_t smem_to_u32(const void* p) {
    uint32_t a;
    asm("{ .reg .u64 tmp; cvta.to.shared.u64 tmp, %1; cvt.u32.u64 %0, tmp; }" : "=r"(a) : "l"(p));
    return a;
}
static __device__ __forceinline__ void cp_async16(uint32_t dst, const void* src) {
    asm volatile("cp.async.cg.shared.global [%0], [%1], 16;" :: "r"(dst), "l"(src) : "memory");
}
static __device__ __forceinline__ void cp_commit() {
    asm volatile("cp.async.commit_group;" ::: "memory");
}
static __device__ __forceinline__ void cp_wait1() {
    asm volatile("cp.async.wait_group 1;" ::: "memory");
}
static __device__ __forceinline__ void cp_wait0() {
    asm volatile("cp.async.wait_group 0;" ::: "memory");
}
static __device__ __forceinline__ void ldmatrix_x4(uint32_t& r0, uint32_t& r1,
                                                   uint32_t& r2, uint32_t& r3, uint32_t a) {
    asm volatile("ldmatrix.sync.aligned.m8n8.x4.shared.b16 {%0,%1,%2,%3}, [%4];"
        : "=r"(r0), "=r"(r1), "=r"(r2), "=r"(r3) : "r"(a));
}
static __device__ __forceinline__ void mma_f16(float* c,
                                               uint32_t a0, uint32_t a1, uint32_t a2, uint32_t a3,
                                               uint32_t b0, uint32_t b1) {
    asm volatile("mma.sync.aligned.m16n8k16.row.col.f32.f16.f16.f32 "
        "{%0,%1,%2,%3}, {%4,%5,%6,%7}, {%8,%9}, {%0,%1,%2,%3};"
        : "+f"(c[0]), "+f"(c[1]), "+f"(c[2]), "+f"(c[3])
        : "r"(a0), "r"(a1), "r"(a2), "r"(a3), "r"(b0), "r"(b1));
}
static __device__ __forceinline__ uint32_t packh(__half a, __half b) {
    return (uint32_t)__half_as_ushort(a) | ((uint32_t)__half_as_ushort(b) << 16);
}
// top-4 tracker update: cached-min fast path, static-index replace
static __device__ __forceinline__ void t4upd(float v, int idx,
        float& a, float& b, float& c, float& d,
        int& ia, int& ib, int& ic, int& id, float& tmin)
{
    if (v > tmin) {
        if (a == tmin)      { a = v; ia = idx; }
        else if (b == tmin) { b = v; ib = idx; }
        else if (c == tmin) { c = v; ic = idx; }
        else                { d = v; id = idx; }
        tmin = fminf(fminf(a, b), fminf(c, d));
    }
}
// exact fp32 dot of token column ts (in sx) with code row e
static __device__ __forceinline__ float exact_dot(const float* __restrict__ e,
                                                  const float* sxp, int ts) {
    float a0 = 0.f, a1 = 0.f, a2 = 0.f, a3 = 0.f;
#pragma unroll
    for (int d0 = 0; d0 < ND; d0 += 4) {
        float4 ev = *reinterpret_cast<const float4*>(e + d0);
        a0 = fmaf(sxp[(d0)     * SX_STRIDE + ts], ev.x, a0);
        a1 = fmaf(sxp[(d0 + 1) * SX_STRIDE + ts], ev.y, a1);
        a2 = fmaf(sxp[(d0 + 2) * SX_STRIDE + ts], ev.z, a2);
        a3 = fmaf(sxp[(d0 + 3) * SX_STRIDE + ts], ev.w, a3);
    }
    return (a0 + a1) + (a2 + a3);
}

// ---------------------------------------------------------------------------
// Kernel 0: codebook -> fp16, padded 144B rows (pad never read by ldmatrix).
// ---------------------------------------------------------------------------
__global__ void vq_prep_kernel(const float* __restrict__ emb)
{
    int i = blockIdx.x * blockDim.x + threadIdx.x;
    if (i >= NK * ND) return;
    int code = i >> 6, d = i & 63;
    g_cb[code * (CBROW/2) + d] = __half_as_ushort(__float2half_rn(emb[i]));
}

// ---------------------------------------------------------------------------
// Kernel 1: fp16 single-product argmax + candidate rescore + fused tail.
// CTA = 64 tokens (8 warps x 8 tokens). Per 16-code tile: 4 LDSM + 4 HMMA
// (score = h.H, err <= 4.9e-4*||x|| hard). Each lane tracks top-4 of its 128
// codes per token; window candidates get exact fp32 rescore; if a lane's
// 4th-best is in-window (possible eviction) -> full warp exact rescan.
// Final selection compares exact values only -> idx exact.
// Tail (from R12): idx write + emb/embu gather + quantized tile + loss.
// ---------------------------------------------------------------------------
__global__ void __launch_bounds__(256, 2) vq_mma_argmax_kernel(
        const float* __restrict__ in, const float* __restrict__ emb,
        const float* __restrict__ embu, float* __restrict__ out)
{
    extern __shared__ float sx[];          // [64 dims][SX_STRIDE] fp32, then code bufs
    const uint32_t sbase = smem_to_u32(sx);
    char* smemc = reinterpret_cast<char*>(sx);
    const int tid  = threadIdx.x;
    const int lane = tid & 31;
    const int w    = tid >> 5;
    const int gid  = lane >> 2;
    const int tig  = lane & 3;

    const int n0 = blockIdx.x * 64;
    const int b  = n0 >> 12;
    const int t0 = n0 & (NT - 1);

    // stage x tile [64 d][64 t] fp32, coalesced
    {
        const float4* src = reinterpret_cast<const float4*>(in + (size_t)b * ND * NT + t0);
#pragma unroll
        for (int k = 0; k < 4; k++) {
            int i = tid + k * 256;
            int d = i >> 4, q = i & 15;
            float4 v = src[(size_t)d * (NT / 4) + q];
            *reinterpret_cast<float4*>(sx + d * SX_STRIDE + q * 4) = v;
        }
    }
    // preload code chunk 0
    for (int i = tid; i < CHUNK_16B; i += 256)
        cp_async16(sbase + SMEM_CB0 + i * 16, (const char*)g_cb + i * 16);
    cp_commit();
    __syncthreads();   // sx visible

    // token-side fp16 fragments (token = w*8 + gid) + ||x||^2
    const int tok = w * 8 + gid;
    uint32_t bh[8];
    float sq = 0.f;
#pragma unroll
    for (int j = 0; j < 4; j++) {
        int d0 = j * 16 + 2 * tig;
        float v0 = sx[d0 * SX_STRIDE + tok];
        float v1 = sx[(d0 + 1) * SX_STRIDE + tok];
        float v2 = sx[(d0 + 8) * SX_STRIDE + tok];
        float v3 = sx[(d0 + 9) * SX_STRIDE + tok];
        sq += v0 * v0 + v1 * v1 + v2 * v2 + v3 * v3;
        bh[2*j]   = packh(__float2half_rn(v0), __float2half_rn(v1));
        bh[2*j+1] = packh(__float2half_rn(v2), __float2half_rn(v3));
    }
    sq += __shfl_xor_sync(0xffffffffu, sq, 1);
    sq += __shfl_xor_sync(0xffffffffu, sq, 2);   // full ||x||^2 of token w*8+gid

    // per-lane top-4 candidate sets for tokens 2*tig (col0) and 2*tig+1 (col1)
    float v00 = -3.0e38f, v01 = -3.0e38f, v02 = -3.0e38f, v03 = -3.0e38f;
    float v10 = -3.0e38f, v11 = -3.0e38f, v12 = -3.0e38f, v13 = -3.0e38f;
    int   i00 = 0, i01 = 0, i02 = 0, i03 = 0;
    int   i10 = 0, i11 = 0, i12 = 0, i13 = 0;
    float tmin0 = -3.0e38f, tmin1 = -3.0e38f;

    const uint32_t lmbase = sbase + (uint32_t)((lane & 15) * CBROW + ((lane >> 4) * 16));

    for (int c = 0; c < NCHUNK; c++) {
        const uint32_t bufo = (c & 1) ? SMEM_CB1 : SMEM_CB0;
        if (c + 1 < NCHUNK) {
            const uint32_t nbufo = (c & 1) ? SMEM_CB0 : SMEM_CB1;
            const char* src = (const char*)g_cb + (size_t)(c + 1) * CHUNK_BYTES;
            for (int i = tid; i < CHUNK_16B; i += 256)
                cp_async16(sbase + nbufo + i * 16, src + i * 16);
            cp_commit();
            cp_wait1();
        } else {
            cp_wait0();
        }
        __syncthreads();

#pragma unroll 2
        for (int mt = 0; mt < 8; mt++) {
            uint32_t lm = lmbase + bufo + (uint32_t)(mt * 16 * CBROW);
            uint32_t AH[16];
#pragma unroll
            for (int jj = 0; jj < 4; jj++)
                ldmatrix_x4(AH[4*jj], AH[4*jj+1], AH[4*jj+2], AH[4*jj+3], lm + jj * 32);
            float cacc[4] = {0.f, 0.f, 0.f, 0.f};
#pragma unroll
            for (int jj = 0; jj < 4; jj++)
                mma_f16(cacc, AH[4*jj], AH[4*jj+1], AH[4*jj+2], AH[4*jj+3],
                        bh[2*jj], bh[2*jj+1]);
            const int ib = c * CHUNK_CODES + mt * 16;
            t4upd(cacc[0], ib + gid,     v00, v01, v02, v03, i00, i01, i02, i03, tmin0);
            t4upd(cacc[2], ib + gid + 8, v00, v01, v02, v03, i00, i01, i02, i03, tmin0);
            t4upd(cacc[1], ib + gid,     v10, v11, v12, v13, i10, i11, i12, i13, tmin1);
            t4upd(cacc[3], ib + gid + 8, v10, v11, v12, v13, i10, i11, i12, i13, tmin1);
        }
        __syncthreads();
    }

    // ===== rescue: windowed exact rescore (+ rare full-rescan fallback) =====
    float vmax0 = fmaxf(fmaxf(v00, v01), fmaxf(v02, v03));
    float vmax1 = fmaxf(fmaxf(v10, v11), fmaxf(v12, v13));
#pragma unroll
    for (int off = 4; off <= 16; off <<= 1) {
        vmax0 = fmaxf(vmax0, __shfl_xor_sync(0xffffffffu, vmax0, off));
        vmax1 = fmaxf(vmax1, __shfl_xor_sync(0xffffffffu, vmax1, off));
    }
    float sqA = __shfl_sync(0xffffffffu, sq, 8 * tig);       // ||x||^2 token 2*tig
    float sqB = __shfl_sync(0xffffffffu, sq, 8 * tig + 4);   // ||x||^2 token 2*tig+1
    const float T0 = vmax0 - WINC * sqrtf(sqA);
    const float T1 = vmax1 - WINC * sqrtf(sqB);
    unsigned mk0 = __ballot_sync(0xffffffffu, tmin0 >= T0);  // possible eviction
    unsigned mk1 = __ballot_sync(0xffffffffu, tmin1 >= T1);

    const int ts0 = w * 8 + 2 * tig;
    const int ts1 = ts0 + 1;
    // exact rescore of in-window candidates; others can't win -> -inf
    v00 = (v00 >= T0) ? exact_dot(emb + (size_t)i00 * ND, sx, ts0) : -3.0e38f;
    v01 = (v01 >= T0) ? exact_dot(emb + (size_t)i01 * ND, sx, ts0) : -3.0e38f;
    v02 = (v02 >= T0) ? exact_dot(emb + (size_t)i02 * ND, sx, ts0) : -3.0e38f;
    v03 = (v03 >= T0) ? exact_dot(emb + (size_t)i03 * ND, sx, ts0) : -3.0e38f;
    v10 = (v10 >= T1) ? exact_dot(emb + (size_t)i10 * ND, sx, ts1) : -3.0e38f;
    v11 = (v11 >= T1) ? exact_dot(emb + (size_t)i11 * ND, sx, ts1) : -3.0e38f;
    v12 = (v12 >= T1) ? exact_dot(emb + (size_t)i12 * ND, sx, ts1) : -3.0e38f;
    v13 = (v13 >= T1) ? exact_dot(emb + (size_t)i13 * ND, sx, ts1) : -3.0e38f;

    // lane-local best (value desc, idx asc)
    float bv0 = v00; int bi0 = i00;
    if (v01 > bv0 || (v01 == bv0 && i01 < bi0)) { bv0 = v01; bi0 = i01; }
    if (v02 > bv0 || (v02 == bv0 && i02 < bi0)) { bv0 = v02; bi0 = i02; }
    if (v03 > bv0 || (v03 == bv0 && i03 < bi0)) { bv0 = v03; bi0 = i03; }
    float bv1 = v10; int bi1 = i10;
    if (v11 > bv1 || (v11 == bv1 && i11 < bi1)) { bv1 = v11; bi1 = i11; }
    if (v12 > bv1 || (v12 == bv1 && i12 < bi1)) { bv1 = v12; bi1 = i12; }
    if (v13 > bv1 || (v13 == bv1 && i13 < bi1)) { bv1 = v13; bi1 = i13; }
    // butterfly across the 8 lanes of each token group (tig preserved)
#pragma unroll
    for (int off = 4; off <= 16; off <<= 1) {
        float ov = __shfl_xor_sync(0xffffffffu, bv0, off);
        int   oi = __shfl_xor_sync(0xffffffffu, bi0, off);
        if (ov > bv0 || (ov == bv0 && oi < bi0)) { bv0 = ov; bi0 = oi; }
        ov = __shfl_xor_sync(0xffffffffu, bv1, off);
        oi = __shfl_xor_sync(0xffffffffu, bi1, off);
        if (ov > bv1 || (ov == bv1 && oi < bi1)) { bv1 = ov; bi1 = oi; }
    }

    // full-rescan fallback (rare): token (t,col) if any of its 8 lanes flagged
    if (mk0 | mk1) {
        for (int t = 0; t < 4; t++) {
#pragma unroll
            for (int col = 0; col < 2; col++) {
                unsigned mk = col ? mk1 : mk0;
                if ((mk >> t) & 0x11111111u) {
                    const int ts = w * 8 + 2 * t + col;
                    float bb = -3.0e38f; int bbi = 0;
                    for (int cc = lane; cc < NK; cc += 32) {
                        const float* e = emb + (size_t)cc * ND;
                        float a0 = 0.f, a1 = 0.f, a2 = 0.f, a3 = 0.f;
#pragma unroll
                        for (int d = 0; d < ND; d += 4) {
                            a0 = fmaf(sx[d * SX_STRIDE + ts],       e[d],     a0);
                            a1 = fmaf(sx[(d + 1) * SX_STRIDE + ts], e[d + 1], a1);
                            a2 = fmaf(sx[(d + 2) * SX_STRIDE + ts], e[d + 2], a2);
                            a3 = fmaf(sx[(d + 3) * SX_STRIDE + ts], e[d + 3], a3);
                        }
                        float v = (a0 + a1) + (a2 + a3);
                        if (v > bb) { bb = v; bbi = cc; }
                    }
#pragma unroll
                    for (int off = 16; off; off >>= 1) {
                        float ov = __shfl_xor_sync(0xffffffffu, bb, off);
                        int   oi = __shfl_xor_sync(0xffffffffu, bbi, off);
                        if (ov > bb || (ov == bb && oi < bbi)) { bb = ov; bbi = oi; }
                    }
                    if (tig == t) { if (col) bi1 = bbi; else bi0 = bbi; }
                }
            }
        }
    }

    // ============ FUSED TAIL: idx write + gather + loss partial ============
    int*   sidx = reinterpret_cast<int*>(smemc + SMEM_CB0);
    float* sq2  = reinterpret_cast<float*>(smemc + SMEM_CB0 + 1024);
    float* su   = reinterpret_cast<float*>(smemc + SMEM_CB1);
    float* ws   = reinterpret_cast<float*>(smemc + SMEM_CB1 + 16640);

    __syncthreads();   // done with chunk buffers & rescue reads of sx
    if (lane < 4) {    // lane l: tig == l, holds tokens 2l and 2l+1
        const int tk = w * 8 + 2 * lane;
        const int n  = n0 + tk;
        sidx[tk]     = bi0;
        sidx[tk + 1] = bi1;
        out[OUTQ + 2 + n]     = (float)bi0;
        out[OUTQ + 2 + n + 1] = (float)bi1;
    }
    __syncthreads();

    // gather emb/embu rows, coalesced on codebook rows (4 threads per token)
    {
        const int gtok = tid >> 2;
        const int qq   = tid & 3;
        const int code = sidx[gtok];
        const float4* e4 = reinterpret_cast<const float4*>(emb  + (size_t)code * ND);
        const float4* u4 = reinterpret_cast<const float4*>(embu + (size_t)code * ND);
#pragma unroll
        for (int j = 0; j < 4; j++) {
            float4 f = e4[qq * 4 + j];
            float4 u = u4[qq * 4 + j];
            int base = gtok * 65 + qq * 16 + j * 4;
            sq2[base] = f.x; sq2[base+1] = f.y; sq2[base+2] = f.z; sq2[base+3] = f.w;
            su[base]  = u.x; su[base+1]  = u.y; su[base+2]  = u.z; su[base+3]  = u.w;
        }
    }
    __syncthreads();

    // write [64 d x 64 t] quantized tile coalesced; loss from sx
    {
        const int d  = tid >> 2;
        const int j0 = (tid & 3) * 16;
        const size_t gbase = (size_t)b * ND * NT + (size_t)d * NT + t0 + j0;
        float lsum = 0.f;
#pragma unroll
        for (int i = 0; i < 16; i++) {
            float xi = sx[d * SX_STRIDE + j0 + i];
            out[gbase + i] = sq2[(j0 + i) * 65 + d];
            float df = xi - su[(j0 + i) * 65 + d];
            lsum += df * df;
        }
#pragma unroll
        for (int o = 16; o; o >>= 1) lsum += __shfl_xor_sync(0xffffffffu, lsum, o);
        if ((tid & 31) == 0) ws[tid >> 5] = lsum;
        __syncthreads();
        if (tid < 32) {
            float v = (tid < 8) ? ws[tid] : 0.f;
#pragma unroll
            for (int o = 4; o; o >>= 1) v += __shfl_xor_sync(0xffffffffu, v, o);
            if (tid == 0) g_part[blockIdx.x] = v;
        }
    }
}

// ---------------------------------------------------------------------------
// Kernel 2: final loss reduction (double precision), write scalars.
// commitment_loss == codebook_loss forward == mean((flat - emb_unnorm[idx])^2)
// ---------------------------------------------------------------------------
__global__ void vq_finalize_kernel(float* __restrict__ out)
{
    __shared__ double sd[256];
    double s = 0.0;
    for (int i = threadIdx.x; i < NPART; i += 256) s += (double)g_part[i];
    sd[threadIdx.x] = s;
    __syncthreads();
    for (int o = 128; o; o >>= 1) {
        if (threadIdx.x < o) sd[threadIdx.x] += sd[threadIdx.x + o];
        __syncthreads();
    }
    if (threadIdx.x == 0) {
        float m = (float)(sd[0] / (double)OUTQ);
        out[OUTQ]     = m;   // commitment_loss
        out[OUTQ + 1] = m;   // codebook_loss (numerically identical forward)
    }
}

extern "C" void kernel_launch(void* const* d_in, const int* in_sizes, int n_in,
                              void* d_out, int out_size) {
    const float* in   = (const float*)d_in[0];   // [32, 64, 4096] fp32
    const float* emb  = (const float*)d_in[1];   // [1024, 64] fp32 (pre-normalized)
    const float* embu = (const float*)d_in[2];   // [1024, 64] fp32
    float* out = (float*)d_out;

    static int configured = 0;
    if (!configured) {
        cudaFuncSetAttribute(vq_mma_argmax_kernel,
                             cudaFuncAttributeMaxDynamicSharedMemorySize, SMEM_TOTAL);
        configured = 1;
    }

    vq_prep_kernel<<<(NK * ND) / 256, 256>>>(emb);
    vq_mma_argmax_kernel<<<NTOK / 64, 256, SMEM_TOTAL>>>(in, emb, embu, out);
    vq_finalize_kernel<<<1, 256>>>(out);
}

// round 14
// speedup vs baseline: 2.6037x; 1.1578x over previous
#include <cuda_runtime.h>
#include <cuda_fp16.h>
#include <cstdint>

#define NB 32
#define ND 64
#define NT 4096
#define NK 1024
#define NTOK (NB*NT)          // 131072 tokens
#define OUTQ (NB*ND*NT)       // 8388608 quantized elements

#define CBROW 144             // bytes per code row: [H(64 fp16) | pad(16)]
#define CHUNK_CODES 128
#define NCHUNK (NK/CHUNK_CODES)                // 8
#define CHUNK_BYTES (CHUNK_CODES*CBROW)        // 18432
#define CHUNK_16B (CHUNK_BYTES/16)             // 1152

#define SXS 132               // floats per dim row (128 tokens + pad, conflict-free)
#define SMEM_SX_BYTES (64*SXS*4)               // 33792
#define SMEM_CB0 SMEM_SX_BYTES                 // 33792
#define SMEM_CB1 (SMEM_CB0 + CHUNK_BYTES)      // 52224
#define SMEM_TOTAL (SMEM_CB1 + CHUNK_BYTES)    // 70656
// post-mainloop overlays (chunk buffers dead):
//   sidx@CB0 (512B); sq2@CB0+1024 (16640B); su@sq2+16640; ws@su+16640 (32B)

#define WINC 1.15e-3f         // window = WINC*||x||; hard err bound 4.9e-4*||x||
#define NPART (NTOK/128)      // 1024 argmax CTAs, one loss partial each

// Scratch (no allocations allowed)
__device__ float          g_part[NPART];
__device__ unsigned short g_cb[NK * (CBROW/2)];   // fp16 codebook, padded rows

// ============================ helpers ============================
static __device__ __forceinline__ uint32_t smem_to_u32(const void* p) {
    uint32_t a;
    asm("{ .reg .u64 tmp; cvta.to.shared.u64 tmp, %1; cvt.u32.u64 %0, tmp; }" : "=r"(a) : "l"(p));
    return a;
}
static __device__ __forceinline__ void cp_async16(uint32_t dst, const void* src) {
    asm volatile("cp.async.cg.shared.global [%0], [%1], 16;" :: "r"(dst), "l"(src) : "memory");
}
static __device__ __forceinline__ void cp_commit() {
    asm volatile("cp.async.commit_group;" ::: "memory");
}
static __device__ __forceinline__ void cp_wait1() {
    asm volatile("cp.async.wait_group 1;" ::: "memory");
}
static __device__ __forceinline__ void cp_wait0() {
    asm volatile("cp.async.wait_group 0;" ::: "memory");
}
static __device__ __forceinline__ void ldmatrix_x4(uint32_t& r0, uint32_t& r1,
                                                   uint32_t& r2, uint32_t& r3, uint32_t a) {
    asm volatile("ldmatrix.sync.aligned.m8n8.x4.shared.b16 {%0,%1,%2,%3}, [%4];"
        : "=r"(r0), "=r"(r1), "=r"(r2), "=r"(r3) : "r"(a));
}
static __device__ __forceinline__ void mma_f16(float* c,
                                               uint32_t a0, uint32_t a1, uint32_t a2, uint32_t a3,
                                               uint32_t b0, uint32_t b1) {
    asm volatile("mma.sync.aligned.m16n8k16.row.col.f32.f16.f16.f32 "
        "{%0,%1,%2,%3}, {%4,%5,%6,%7}, {%8,%9}, {%0,%1,%2,%3};"
        : "+f"(c[0]), "+f"(c[1]), "+f"(c[2]), "+f"(c[3])
        : "r"(a0), "r"(a1), "r"(a2), "r"(a3), "r"(b0), "r"(b1));
}
static __device__ __forceinline__ uint32_t packh(__half a, __half b) {
    return (uint32_t)__half_as_ushort(a) | ((uint32_t)__half_as_ushort(b) << 16);
}
// exact fp32 dot of token column ts (in sx) with code row e
static __device__ __forceinline__ float exact_dot(const float* __restrict__ e,
                                                  const float* sxp, int ts) {
    float a0 = 0.f, a1 = 0.f, a2 = 0.f, a3 = 0.f;
#pragma unroll
    for (int d0 = 0; d0 < ND; d0 += 4) {
        float4 ev = *reinterpret_cast<const float4*>(e + d0);
        a0 = fmaf(sxp[(d0)     * SXS + ts], ev.x, a0);
        a1 = fmaf(sxp[(d0 + 1) * SXS + ts], ev.y, a1);
        a2 = fmaf(sxp[(d0 + 2) * SXS + ts], ev.z, a2);
        a3 = fmaf(sxp[(d0 + 3) * SXS + ts], ev.w, a3);
    }
    return (a0 + a1) + (a2 + a3);
}

// top-3 tracker update (k must be a compile-time constant at each use)
#define T3UPD(v, idx, k) do {                                              \
    float _v = (v);                                                        \
    if (_v > tmin[k]) {                                                    \
        if (tv[k][0] == tmin[k])      { tv[k][0] = _v; ti_[k][0] = (idx); }\
        else if (tv[k][1] == tmin[k]) { tv[k][1] = _v; ti_[k][1] = (idx); }\
        else                          { tv[k][2] = _v; ti_[k][2] = (idx); }\
        tmin[k] = fminf(tv[k][0], fminf(tv[k][1], tv[k][2]));              \
    }                                                                      \
} while (0)

// ---------------------------------------------------------------------------
// Kernel 0: codebook -> fp16, padded 144B rows.
// ---------------------------------------------------------------------------
__global__ void vq_prep_kernel(const float* __restrict__ emb)
{
    int i = blockIdx.x * blockDim.x + threadIdx.x;
    if (i >= NK * ND) return;
    int code = i >> 6, d = i & 63;
    g_cb[code * (CBROW/2) + d] = __half_as_ushort(__float2half_rn(emb[i]));
}

// ---------------------------------------------------------------------------
// Kernel 1: fp16 argmax, A-fragment reused over 2 token groups, + fused tail.
// CTA = 128 tokens (8 warps x 16). Per 16-code tile: 4 LDSM + 8 HMMA in 2
// independent chains (score = h.H, err <= 4.9e-4*||x|| hard). Top-3/lane
// candidate sets; in-window candidates exact-rescored; possible-eviction ->
// full warp exact rescan. Final selection on exact values only -> idx exact.
// Tail: idx write + emb/embu gather + quantized tile + loss, in 2 halves.
// ---------------------------------------------------------------------------
__global__ void __launch_bounds__(256, 2) vq_mma_argmax_kernel(
        const float* __restrict__ in, const float* __restrict__ emb,
        const float* __restrict__ embu, float* __restrict__ out)
{
    extern __shared__ float sx[];
    const uint32_t sbase = smem_to_u32(sx);
    char* smemc = reinterpret_cast<char*>(sx);
    const int tid  = threadIdx.x;
    const int lane = tid & 31;
    const int w    = tid >> 5;
    const int gid  = lane >> 2;
    const int tig  = lane & 3;

    const int n0 = blockIdx.x * 128;
    const int b  = n0 >> 12;
    const int t0 = n0 & (NT - 1);

    // stage x tile [64 d][128 t] fp32, coalesced
    {
        const float4* src = reinterpret_cast<const float4*>(in + (size_t)b * ND * NT + t0);
#pragma unroll
        for (int k = 0; k < 8; k++) {
            int i = tid + k * 256;
            int d = i >> 5, q = i & 31;
            float4 v = src[(size_t)d * (NT / 4) + q];
            *reinterpret_cast<float4*>(sx + d * SXS + q * 4) = v;
        }
    }
    for (int i = tid; i < CHUNK_16B; i += 256)
        cp_async16(sbase + SMEM_CB0 + i * 16, (const char*)g_cb + i * 16);
    cp_commit();
    __syncthreads();   // sx visible

    // fp16 fragments for both token groups + ||x||^2 per owned token
    const int tokA = w * 16 + gid;
    const int tokB = tokA + 8;
    uint32_t bhA[8], bhB[8];
    float sqA = 0.f, sqB = 0.f;
#pragma unroll
    for (int j = 0; j < 4; j++) {
        int d0 = j * 16 + 2 * tig;
        float a0 = sx[d0 * SXS + tokA],       a1 = sx[(d0 + 1) * SXS + tokA];
        float a2 = sx[(d0 + 8) * SXS + tokA], a3 = sx[(d0 + 9) * SXS + tokA];
        float b0 = sx[d0 * SXS + tokB],       b1 = sx[(d0 + 1) * SXS + tokB];
        float b2 = sx[(d0 + 8) * SXS + tokB], b3 = sx[(d0 + 9) * SXS + tokB];
        sqA += a0*a0 + a1*a1 + a2*a2 + a3*a3;
        sqB += b0*b0 + b1*b1 + b2*b2 + b3*b3;
        bhA[2*j]   = packh(__float2half_rn(a0), __float2half_rn(a1));
        bhA[2*j+1] = packh(__float2half_rn(a2), __float2half_rn(a3));
        bhB[2*j]   = packh(__float2half_rn(b0), __float2half_rn(b1));
        bhB[2*j+1] = packh(__float2half_rn(b2), __float2half_rn(b3));
    }
    sqA += __shfl_xor_sync(0xffffffffu, sqA, 1);
    sqA += __shfl_xor_sync(0xffffffffu, sqA, 2);
    sqB += __shfl_xor_sync(0xffffffffu, sqB, 1);
    sqB += __shfl_xor_sync(0xffffffffu, sqB, 2);

    // trackers k: 0=(A,col0) 1=(A,col1) 2=(B,col0) 3=(B,col1)
    float tv[4][3]; int ti_[4][3]; float tmin[4];
#pragma unroll
    for (int k = 0; k < 4; k++) {
        tmin[k] = -3.0e38f;
#pragma unroll
        for (int j = 0; j < 3; j++) { tv[k][j] = -3.0e38f; ti_[k][j] = 0; }
    }

    const uint32_t lmbase = sbase + (uint32_t)((lane & 15) * CBROW + ((lane >> 4) * 16));

    for (int c = 0; c < NCHUNK; c++) {
        const uint32_t bufo = (c & 1) ? SMEM_CB1 : SMEM_CB0;
        if (c + 1 < NCHUNK) {
            const uint32_t nbufo = (c & 1) ? SMEM_CB0 : SMEM_CB1;
            const char* src = (const char*)g_cb + (size_t)(c + 1) * CHUNK_BYTES;
            for (int i = tid; i < CHUNK_16B; i += 256)
                cp_async16(sbase + nbufo + i * 16, src + i * 16);
            cp_commit();
            cp_wait1();
        } else {
            cp_wait0();
        }
        __syncthreads();

#pragma unroll 2
        for (int mt = 0; mt < 8; mt++) {
            uint32_t lm = lmbase + bufo + (uint32_t)(mt * 16 * CBROW);
            uint32_t AH[16];
#pragma unroll
            for (int jj = 0; jj < 4; jj++)
                ldmatrix_x4(AH[4*jj], AH[4*jj+1], AH[4*jj+2], AH[4*jj+3], lm + jj * 32);
            float cA[4] = {0.f, 0.f, 0.f, 0.f};
            float cB[4] = {0.f, 0.f, 0.f, 0.f};
#pragma unroll
            for (int jj = 0; jj < 4; jj++) {
                mma_f16(cA, AH[4*jj], AH[4*jj+1], AH[4*jj+2], AH[4*jj+3],
                        bhA[2*jj], bhA[2*jj+1]);
                mma_f16(cB, AH[4*jj], AH[4*jj+1], AH[4*jj+2], AH[4*jj+3],
                        bhB[2*jj], bhB[2*jj+1]);
            }
            const int ib = c * CHUNK_CODES + mt * 16;
            T3UPD(cA[0], ib + gid,     0); T3UPD(cA[2], ib + gid + 8, 0);
            T3UPD(cA[1], ib + gid,     1); T3UPD(cA[3], ib + gid + 8, 1);
            T3UPD(cB[0], ib + gid,     2); T3UPD(cB[2], ib + gid + 8, 2);
            T3UPD(cB[1], ib + gid,     3); T3UPD(cB[3], ib + gid + 8, 3);
        }
        __syncthreads();
    }

    // ===== rescue: windowed exact rescore (+ rare full-rescan fallback) =====
    float T[4]; unsigned mk[4]; float bv[4]; int bi[4];
#pragma unroll
    for (int k = 0; k < 4; k++) {
        float vmax = fmaxf(tv[k][0], fmaxf(tv[k][1], tv[k][2]));
#pragma unroll
        for (int off = 4; off <= 16; off <<= 1)
            vmax = fmaxf(vmax, __shfl_xor_sync(0xffffffffu, vmax, off));
        float sq_tok = __shfl_sync(0xffffffffu, (k < 2) ? sqA : sqB,
                                   8 * tig + 4 * (k & 1));
        T[k] = vmax - WINC * sqrtf(sq_tok);
        mk[k] = __ballot_sync(0xffffffffu, tmin[k] >= T[k]);

        const int ts = w * 16 + (k >> 1) * 8 + 2 * tig + (k & 1);
#pragma unroll
        for (int j = 0; j < 3; j++)
            tv[k][j] = (tv[k][j] >= T[k])
                     ? exact_dot(emb + (size_t)ti_[k][j] * ND, sx, ts) : -3.0e38f;

        bv[k] = tv[k][0]; bi[k] = ti_[k][0];
        if (tv[k][1] > bv[k] || (tv[k][1] == bv[k] && ti_[k][1] < bi[k]))
            { bv[k] = tv[k][1]; bi[k] = ti_[k][1]; }
        if (tv[k][2] > bv[k] || (tv[k][2] == bv[k] && ti_[k][2] < bi[k]))
            { bv[k] = tv[k][2]; bi[k] = ti_[k][2]; }
#pragma unroll
        for (int off = 4; off <= 16; off <<= 1) {
            float ov = __shfl_xor_sync(0xffffffffu, bv[k], off);
            int   oi = __shfl_xor_sync(0xffffffffu, bi[k], off);
            if (ov > bv[k] || (ov == bv[k] && oi < bi[k])) { bv[k] = ov; bi[k] = oi; }
        }
    }

    if (mk[0] | mk[1] | mk[2] | mk[3]) {
#pragma unroll
        for (int k = 0; k < 4; k++) {
            for (int t = 0; t < 4; t++) {
                if ((mk[k] >> t) & 0x11111111u) {
                    const int ts = w * 16 + (k >> 1) * 8 + 2 * t + (k & 1);
                    float bb = -3.0e38f; int bbi = 0;
                    for (int cc = lane; cc < NK; cc += 32) {
                        float v = exact_dot(emb + (size_t)cc * ND, sx, ts);
                        if (v > bb) { bb = v; bbi = cc; }
                    }
#pragma unroll
                    for (int off = 16; off; off >>= 1) {
                        float ov = __shfl_xor_sync(0xffffffffu, bb, off);
                        int   oi = __shfl_xor_sync(0xffffffffu, bbi, off);
                        if (ov > bb || (ov == bb && oi < bbi)) { bb = ov; bbi = oi; }
                    }
                    if (tig == t) bi[k] = bbi;
                }
            }
        }
    }

    // ============ FUSED TAIL: idx write + gather + loss (2 halves) ============
    int*   sidx = reinterpret_cast<int*>(smemc + SMEM_CB0);
    float* sq2  = reinterpret_cast<float*>(smemc + SMEM_CB0 + 1024);
    float* su   = reinterpret_cast<float*>(smemc + SMEM_CB0 + 1024 + 16640);
    float* ws   = reinterpret_cast<float*>(smemc + SMEM_CB0 + 1024 + 2 * 16640);

    __syncthreads();   // done with chunk buffers & rescue reads of sx
    if (lane < 4) {    // lane l (tig==l) holds tokens 2l,2l+1 (A) and +8 (B)
        const int tkA = w * 16 + 2 * lane;
        sidx[tkA]         = bi[0];
        sidx[tkA + 1]     = bi[1];
        sidx[tkA + 8]     = bi[2];
        sidx[tkA + 9]     = bi[3];
        const int n = n0 + tkA;
        out[OUTQ + 2 + n]     = (float)bi[0];
        out[OUTQ + 2 + n + 1] = (float)bi[1];
        out[OUTQ + 2 + n + 8] = (float)bi[2];
        out[OUTQ + 2 + n + 9] = (float)bi[3];
    }

    float lsum = 0.f;
    for (int half = 0; half < 2; half++) {
        __syncthreads();
        // gather emb/embu rows for tokens [half*64, half*64+64)
        {
            const int gtok = tid >> 2;
            const int qq   = tid & 3;
            const int code = sidx[half * 64 + gtok];
            const float4* e4 = reinterpret_cast<const float4*>(emb  + (size_t)code * ND);
            const float4* u4 = reinterpret_cast<const float4*>(embu + (size_t)code * ND);
#pragma unroll
            for (int j = 0; j < 4; j++) {
                float4 f = e4[qq * 4 + j];
                float4 u = u4[qq * 4 + j];
                int base = gtok * 65 + qq * 16 + j * 4;
                sq2[base] = f.x; sq2[base+1] = f.y; sq2[base+2] = f.z; sq2[base+3] = f.w;
                su[base]  = u.x; su[base+1]  = u.y; su[base+2]  = u.z; su[base+3]  = u.w;
            }
        }
        __syncthreads();
        // write quantized [64 d x 64 t] coalesced; loss from sx
        {
            const int d  = tid >> 2;
            const int j0 = (tid & 3) * 16;
            const size_t gbase = (size_t)b * ND * NT + (size_t)d * NT + t0 + half * 64 + j0;
#pragma unroll
            for (int i = 0; i < 16; i++) {
                float xi = sx[d * SXS + half * 64 + j0 + i];
                out[gbase + i] = sq2[(j0 + i) * 65 + d];
                float df = xi - su[(j0 + i) * 65 + d];
                lsum += df * df;
            }
        }
    }
#pragma unroll
    for (int o = 16; o; o >>= 1) lsum += __shfl_xor_sync(0xffffffffu, lsum, o);
    if ((tid & 31) == 0) ws[tid >> 5] = lsum;
    __syncthreads();
    if (tid < 32) {
        float v = (tid < 8) ? ws[tid] : 0.f;
#pragma unroll
        for (int o = 4; o; o >>= 1) v += __shfl_xor_sync(0xffffffffu, v, o);
        if (tid == 0) g_part[blockIdx.x] = v;
    }
}

// ---------------------------------------------------------------------------
// Kernel 2: final loss reduction (double precision), write scalars.
// commitment_loss == codebook_loss forward == mean((flat - emb_unnorm[idx])^2)
// ---------------------------------------------------------------------------
__global__ void vq_finalize_kernel(float* __restrict__ out)
{
    __shared__ double sd[256];
    double s = 0.0;
    for (int i = threadIdx.x; i < NPART; i += 256) s += (double)g_part[i];
    sd[threadIdx.x] = s;
    __syncthreads();
    for (int o = 128; o; o >>= 1) {
        if (threadIdx.x < o) sd[threadIdx.x] += sd[threadIdx.x + o];
        __syncthreads();
    }
    if (threadIdx.x == 0) {
        float m = (float)(sd[0] / (double)OUTQ);
        out[OUTQ]     = m;   // commitment_loss
        out[OUTQ + 1] = m;   // codebook_loss (numerically identical forward)
    }
}

extern "C" void kernel_launch(void* const* d_in, const int* in_sizes, int n_in,
                              void* d_out, int out_size) {
    const float* in   = (const float*)d_in[0];   // [32, 64, 4096] fp32
    const float* emb  = (const float*)d_in[1];   // [1024, 64] fp32 (pre-normalized)
    const float* embu = (const float*)d_in[2];   // [1024, 64] fp32
    float* out = (float*)d_out;

    static int configured = 0;
    if (!configured) {
        cudaFuncSetAttribute(vq_mma_argmax_kernel,
                             cudaFuncAttributeMaxDynamicSharedMemorySize, SMEM_TOTAL);
        configured = 1;
    }

    vq_prep_kernel<<<(NK * ND) / 256, 256>>>(emb);
    vq_mma_argmax_kernel<<<NTOK / 128, 256, SMEM_TOTAL>>>(in, emb, embu, out);
    vq_finalize_kernel<<<1, 256>>>(out);
}

// round 16
// speedup vs baseline: 2.7052x; 1.0389x over previous
#include <cuda_runtime.h>
#include <cuda_fp16.h>
#include <cstdint>

#define NB 32
#define ND 64
#define NT 4096
#define NK 1024
#define NTOK (NB*NT)          // 131072 tokens
#define OUTQ (NB*ND*NT)       // 8388608 quantized elements

#define CBROW 144             // bytes per code row: [H(64 fp16) | pad(16)]
#define CHUNK_CODES 128
#define NCHUNK (NK/CHUNK_CODES)                // 8
#define CHUNK_BYTES (CHUNK_CODES*CBROW)        // 18432
#define CHUNK_16B (CHUNK_BYTES/16)             // 1152

#define SXS 260               // floats per dim row (256 tokens + pad, conflict-free)
#define SMEM_SX_BYTES (64*SXS*4)               // 66560
#define SMEM_CB0 SMEM_SX_BYTES                 // 66560
#define SMEM_CB1 (SMEM_CB0 + CHUNK_BYTES)      // 84992
#define SMEM_TOTAL (SMEM_CB1 + CHUNK_BYTES)    // 103424  (occ 2: 206848 <= 227KB)
// post-mainloop overlays (chunk buffers dead):
//   sidx@CB0 (1024B); sq2@CB0+1024 (16640B); su@+16640; ws@+16640 (32B)

#define WINC 1.15e-3f         // window = WINC*||x||; hard err bound 4.9e-4*||x||
#define NPART (NTOK/256)      // 512 argmax CTAs, one loss partial each

// Scratch (no allocations allowed)
__device__ float          g_part[NPART];
__device__ unsigned short g_cb[NK * (CBROW/2)];   // fp16 codebook, padded rows

// ============================ helpers ============================
static __device__ __forceinline__ uint32_t smem_to_u32(const void* p) {
    uint32_t a;
    asm("{ .reg .u64 tmp; cvta.to.shared.u64 tmp, %1; cvt.u32.u64 %0, tmp; }" : "=r"(a) : "l"(p));
    return a;
}
static __device__ __forceinline__ void cp_async16(uint32_t dst, const void* src) {
    asm volatile("cp.async.cg.shared.global [%0], [%1], 16;" :: "r"(dst), "l"(src) : "memory");
}
static __device__ __forceinline__ void cp_commit() {
    asm volatile("cp.async.commit_group;" ::: "memory");
}
static __device__ __forceinline__ void cp_wait1() {
    asm volatile("cp.async.wait_group 1;" ::: "memory");
}
static __device__ __forceinline__ void cp_wait0() {
    asm volatile("cp.async.wait_group 0;" ::: "memory");
}
static __device__ __forceinline__ void ldmatrix_x4(uint32_t& r0, uint32_t& r1,
                                                   uint32_t& r2, uint32_t& r3, uint32_t a) {
    asm volatile("ldmatrix.sync.aligned.m8n8.x4.shared.b16 {%0,%1,%2,%3}, [%4];"
        : "=r"(r0), "=r"(r1), "=r"(r2), "=r"(r3) : "r"(a));
}
static __device__ __forceinline__ void mma_f16(float* c,
                                               uint32_t a0, uint32_t a1, uint32_t a2, uint32_t a3,
                                               uint32_t b0, uint32_t b1) {
    asm volatile("mma.sync.aligned.m16n8k16.row.col.f32.f16.f16.f32 "
        "{%0,%1,%2,%3}, {%4,%5,%6,%7}, {%8,%9}, {%0,%1,%2,%3};"
        : "+f"(c[0]), "+f"(c[1]), "+f"(c[2]), "+f"(c[3])
        : "r"(a0), "r"(a1), "r"(a2), "r"(a3), "r"(b0), "r"(b1));
}
static __device__ __forceinline__ uint32_t packh(__half a, __half b) {
    return (uint32_t)__half_as_ushort(a) | ((uint32_t)__half_as_ushort(b) << 16);
}
// exact fp32 dot of token column ts (in sx) with code row e
static __device__ __forceinline__ float exact_dot(const float* __restrict__ e,
                                                  const float* sxp, int ts) {
    float a0 = 0.f, a1 = 0.f, a2 = 0.f, a3 = 0.f;
#pragma unroll
    for (int d0 = 0; d0 < ND; d0 += 4) {
        float4 ev = *reinterpret_cast<const float4*>(e + d0);
        a0 = fmaf(sxp[(d0)     * SXS + ts], ev.x, a0);
        a1 = fmaf(sxp[(d0 + 1) * SXS + ts], ev.y, a1);
        a2 = fmaf(sxp[(d0 + 2) * SXS + ts], ev.z, a2);
        a3 = fmaf(sxp[(d0 + 3) * SXS + ts], ev.w, a3);
    }
    return (a0 + a1) + (a2 + a3);
}

// top-2 tracker update (k compile-time constant at each use)
#define T2UPD(v, idx, k) do {                                              \
    float _v = (v);                                                        \
    if (_v > tmin[k]) {                                                    \
        if (tv[k][0] == tmin[k]) { tv[k][0] = _v; ti_[k][0] = (idx); }     \
        else                     { tv[k][1] = _v; ti_[k][1] = (idx); }     \
        tmin[k] = fminf(tv[k][0], tv[k][1]);                               \
    }                                                                      \
} while (0)

// ---------------------------------------------------------------------------
// Kernel 0: codebook -> fp16, padded 144B rows.
// ---------------------------------------------------------------------------
__global__ void vq_prep_kernel(const float* __restrict__ emb)
{
    int i = blockIdx.x * blockDim.x + threadIdx.x;
    if (i >= NK * ND) return;
    int code = i >> 6, d = i & 63;
    g_cb[code * (CBROW/2) + d] = __half_as_ushort(__float2half_rn(emb[i]));
}

// ---------------------------------------------------------------------------
// Kernel 1: fp16 argmax, A-fragment reused over 4 token groups, + fused tail.
// CTA = 256 tokens (8 warps x 32). Per 16-code tile: 4 LDSM (loaded per
// k-step, 4 regs live) + 16 HMMA in 4 independent chains (score = h.H,
// err <= 4.9e-4*||x|| hard). Top-2/lane candidate sets; in-window candidates
// exact-rescored; possible-eviction -> full warp exact rescan. Selection on
// exact values only -> idx exact. Tail: idx + gather + quantized + loss, 4 qtrs.
// ---------------------------------------------------------------------------
__global__ void __launch_bounds__(256, 2) vq_mma_argmax_kernel(
        const float* __restrict__ in, const float* __restrict__ emb,
        const float* __restrict__ embu, float* __restrict__ out)
{
    extern __shared__ float sx[];
    const uint32_t sbase = smem_to_u32(sx);
    char* smemc = reinterpret_cast<char*>(sx);
    const int tid  = threadIdx.x;
    const int lane = tid & 31;
    const int w    = tid >> 5;
    const int gid  = lane >> 2;
    const int tig  = lane & 3;

    const int n0 = blockIdx.x * 256;
    const int b  = n0 >> 12;
    const int t0 = n0 & (NT - 1);

    // stage x tile [64 d][256 t] fp32, coalesced
    {
        const float4* src = reinterpret_cast<const float4*>(in + (size_t)b * ND * NT + t0);
#pragma unroll
        for (int k = 0; k < 16; k++) {
            int i = tid + k * 256;
            int d = i >> 6, q = i & 63;
            float4 v = src[(size_t)d * (NT / 4) + q];
            *reinterpret_cast<float4*>(sx + d * SXS + q * 4) = v;
        }
    }
    for (int i = tid; i < CHUNK_16B; i += 256)
        cp_async16(sbase + SMEM_CB0 + i * 16, (const char*)g_cb + i * 16);
    cp_commit();
    __syncthreads();   // sx visible

    // fp16 fragments for 4 token groups + ||x||^2 per owned token
    uint32_t bh[4][8];
    float sqg[4];
#pragma unroll
    for (int g = 0; g < 4; g++) {
        const int tok = w * 32 + g * 8 + gid;
        float s = 0.f;
#pragma unroll
        for (int j = 0; j < 4; j++) {
            int d0 = j * 16 + 2 * tig;
            float a0 = sx[d0 * SXS + tok],       a1 = sx[(d0 + 1) * SXS + tok];
            float a2 = sx[(d0 + 8) * SXS + tok], a3 = sx[(d0 + 9) * SXS + tok];
            s += a0*a0 + a1*a1 + a2*a2 + a3*a3;
            bh[g][2*j]   = packh(__float2half_rn(a0), __float2half_rn(a1));
            bh[g][2*j+1] = packh(__float2half_rn(a2), __float2half_rn(a3));
        }
        s += __shfl_xor_sync(0xffffffffu, s, 1);
        s += __shfl_xor_sync(0xffffffffu, s, 2);
        sqg[g] = s;
    }

    // trackers k = 2*g + col
    float tv[8][2]; int ti_[8][2]; float tmin[8];
#pragma unroll
    for (int k = 0; k < 8; k++) {
        tmin[k] = -3.0e38f;
        tv[k][0] = tv[k][1] = -3.0e38f;
        ti_[k][0] = ti_[k][1] = 0;
    }

    const uint32_t lmbase = sbase + (uint32_t)((lane & 15) * CBROW + ((lane >> 4) * 16));

    for (int c = 0; c < NCHUNK; c++) {
        const uint32_t bufo = (c & 1) ? SMEM_CB1 : SMEM_CB0;
        if (c + 1 < NCHUNK) {
            const uint32_t nbufo = (c & 1) ? SMEM_CB0 : SMEM_CB1;
            const char* src = (const char*)g_cb + (size_t)(c + 1) * CHUNK_BYTES;
            for (int i = tid; i < CHUNK_16B; i += 256)
                cp_async16(sbase + nbufo + i * 16, src + i * 16);
            cp_commit();
            cp_wait1();
        } else {
            cp_wait0();
        }
        __syncthreads();

#pragma unroll 2
        for (int mt = 0; mt < 8; mt++) {
            uint32_t lm = lmbase + bufo + (uint32_t)(mt * 16 * CBROW);
            float cc0[4] = {0.f,0.f,0.f,0.f};
            float cc1[4] = {0.f,0.f,0.f,0.f};
            float cc2[4] = {0.f,0.f,0.f,0.f};
            float cc3[4] = {0.f,0.f,0.f,0.f};
#pragma unroll
            for (int jj = 0; jj < 4; jj++) {
                uint32_t a0, a1, a2, a3;
                ldmatrix_x4(a0, a1, a2, a3, lm + jj * 32);
                mma_f16(cc0, a0, a1, a2, a3, bh[0][2*jj], bh[0][2*jj+1]);
                mma_f16(cc1, a0, a1, a2, a3, bh[1][2*jj], bh[1][2*jj+1]);
                mma_f16(cc2, a0, a1, a2, a3, bh[2][2*jj], bh[2][2*jj+1]);
                mma_f16(cc3, a0, a1, a2, a3, bh[3][2*jj], bh[3][2*jj+1]);
            }
            const int ib = c * CHUNK_CODES + mt * 16;
            T2UPD(cc0[0], ib + gid,     0); T2UPD(cc0[2], ib + gid + 8, 0);
            T2UPD(cc0[1], ib + gid,     1); T2UPD(cc0[3], ib + gid + 8, 1);
            T2UPD(cc1[0], ib + gid,     2); T2UPD(cc1[2], ib + gid + 8, 2);
            T2UPD(cc1[1], ib + gid,     3); T2UPD(cc1[3], ib + gid + 8, 3);
            T2UPD(cc2[0], ib + gid,     4); T2UPD(cc2[2], ib + gid + 8, 4);
            T2UPD(cc2[1], ib + gid,     5); T2UPD(cc2[3], ib + gid + 8, 5);
            T2UPD(cc3[0], ib + gid,     6); T2UPD(cc3[2], ib + gid + 8, 6);
            T2UPD(cc3[1], ib + gid,     7); T2UPD(cc3[3], ib + gid + 8, 7);
        }
        __syncthreads();
    }

    // ===== rescue: windowed exact rescore (+ rare full-rescan fallback) =====
    unsigned mk[8]; int bi[8];
#pragma unroll
    for (int k = 0; k < 8; k++) {
        float vmax = fmaxf(tv[k][0], tv[k][1]);
#pragma unroll
        for (int off = 4; off <= 16; off <<= 1)
            vmax = fmaxf(vmax, __shfl_xor_sync(0xffffffffu, vmax, off));
        float sq_tok = __shfl_sync(0xffffffffu, sqg[k >> 1], 8 * tig + 4 * (k & 1));
        const float T = vmax - WINC * sqrtf(sq_tok);
        mk[k] = __ballot_sync(0xffffffffu, tmin[k] >= T);

        const int ts = w * 32 + (k >> 1) * 8 + 2 * tig + (k & 1);
        float e0 = (tv[k][0] >= T)
                 ? exact_dot(emb + (size_t)ti_[k][0] * ND, sx, ts) : -3.0e38f;
        float e1 = (tv[k][1] >= T)
                 ? exact_dot(emb + (size_t)ti_[k][1] * ND, sx, ts) : -3.0e38f;
        float bv = e0; int bidx = ti_[k][0];
        if (e1 > bv || (e1 == bv && ti_[k][1] < bidx)) { bv = e1; bidx = ti_[k][1]; }
#pragma unroll
        for (int off = 4; off <= 16; off <<= 1) {
            float ov = __shfl_xor_sync(0xffffffffu, bv, off);
            int   oi = __shfl_xor_sync(0xffffffffu, bidx, off);
            if (ov > bv || (ov == bv && oi < bidx)) { bv = ov; bidx = oi; }
        }
        bi[k] = bidx;
    }

    if (mk[0] | mk[1] | mk[2] | mk[3] | mk[4] | mk[5] | mk[6] | mk[7]) {
#pragma unroll
        for (int k = 0; k < 8; k++) {
            for (int t = 0; t < 4; t++) {
                if ((mk[k] >> t) & 0x11111111u) {
                    const int ts = w * 32 + (k >> 1) * 8 + 2 * t + (k & 1);
                    float bb = -3.0e38f; int bbi = 0;
                    for (int cc = lane; cc < NK; cc += 32) {
                        float v = exact_dot(emb + (size_t)cc * ND, sx, ts);
                        if (v > bb) { bb = v; bbi = cc; }
                    }
#pragma unroll
                    for (int off = 16; off; off >>= 1) {
                        float ov = __shfl_xor_sync(0xffffffffu, bb, off);
                        int   oi = __shfl_xor_sync(0xffffffffu, bbi, off);
                        if (ov > bb || (ov == bb && oi < bbi)) { bb = ov; bbi = oi; }
                    }
                    if (tig == t) bi[k] = bbi;
                }
            }
        }
    }

    // ============ FUSED TAIL: idx write + gather + loss (4 quarters) ============
    int*   sidx = reinterpret_cast<int*>(smemc + SMEM_CB0);
    float* sq2  = reinterpret_cast<float*>(smemc + SMEM_CB0 + 1024);
    float* su   = reinterpret_cast<float*>(smemc + SMEM_CB0 + 1024 + 16640);
    float* ws   = reinterpret_cast<float*>(smemc + SMEM_CB0 + 1024 + 2 * 16640);

    __syncthreads();   // done with chunk buffers & rescue reads of sx
    if (lane < 4) {    // lane l (tig==l, gid==0) owns tokens g*8 + 2l + c
#pragma unroll
        for (int k = 0; k < 8; k++) {
            const int tk = w * 32 + (k >> 1) * 8 + 2 * lane + (k & 1);
            sidx[tk] = bi[k];
            out[OUTQ + 2 + n0 + tk] = (float)bi[k];
        }
    }

    float lsum = 0.f;
    for (int qtr = 0; qtr < 4; qtr++) {
        __syncthreads();
        // gather emb/embu rows for tokens [qtr*64, qtr*64+64)
        {
            const int gtok = tid >> 2;
            const int qq   = tid & 3;
            const int code = sidx[qtr * 64 + gtok];
            const float4* e4 = reinterpret_cast<const float4*>(emb  + (size_t)code * ND);
            const float4* u4 = reinterpret_cast<const float4*>(embu + (size_t)code * ND);
#pragma unroll
            for (int j = 0; j < 4; j++) {
                float4 f = e4[qq * 4 + j];
                float4 u = u4[qq * 4 + j];
                int base = gtok * 65 + qq * 16 + j * 4;
                sq2[base] = f.x; sq2[base+1] = f.y; sq2[base+2] = f.z; sq2[base+3] = f.w;
                su[base]  = u.x; su[base+1]  = u.y; su[base+2]  = u.z; su[base+3]  = u.w;
            }
        }
        __syncthreads();
        // write quantized [64 d x 64 t] coalesced; loss from sx
        {
            const int d  = tid >> 2;
            const int j0 = (tid & 3) * 16;
            const size_t gbase = (size_t)b * ND * NT + (size_t)d * NT + t0 + qtr * 64 + j0;
#pragma unroll
            for (int i = 0; i < 16; i++) {
                float xi = sx[d * SXS + qtr * 64 + j0 + i];
                out[gbase + i] = sq2[(j0 + i) * 65 + d];
                float df = xi - su[(j0 + i) * 65 + d];
                lsum += df * df;
            }
        }
    }
#pragma unroll
    for (int o = 16; o; o >>= 1) lsum += __shfl_xor_sync(0xffffffffu, lsum, o);
    if ((tid & 31) == 0) ws[tid >> 5] = lsum;
    __syncthreads();
    if (tid < 32) {
        float v = (tid < 8) ? ws[tid] : 0.f;
#pragma unroll
        for (int o = 4; o; o >>= 1) v += __shfl_xor_sync(0xffffffffu, v, o);
        if (tid == 0) g_part[blockIdx.x] = v;
    }
}

// ---------------------------------------------------------------------------
// Kernel 2: final loss reduction (double precision), write scalars.
// commitment_loss == codebook_loss forward == mean((flat - emb_unnorm[idx])^2)
// ---------------------------------------------------------------------------
__global__ void vq_finalize_kernel(float* __restrict__ out)
{
    __shared__ double sd[256];
    double s = 0.0;
    for (int i = threadIdx.x; i < NPART; i += 256) s += (double)g_part[i];
    sd[threadIdx.x] = s;
    __syncthreads();
    for (int o = 128; o; o >>= 1) {
        if (threadIdx.x < o) sd[threadIdx.x] += sd[threadIdx.x + o];
        __syncthreads();
    }
    if (threadIdx.x == 0) {
        float m = (float)(sd[0] / (double)OUTQ);
        out[OUTQ]     = m;   // commitment_loss
        out[OUTQ + 1] = m;   // codebook_loss (numerically identical forward)
    }
}

extern "C" void kernel_launch(void* const* d_in, const int* in_sizes, int n_in,
                              void* d_out, int out_size) {
    const float* in   = (const float*)d_in[0];   // [32, 64, 4096] fp32
    const float* emb  = (const float*)d_in[1];   // [1024, 64] fp32 (pre-normalized)
    const float* embu = (const float*)d_in[2];   // [1024, 64] fp32
    float* out = (float*)d_out;

    static int configured = 0;
    if (!configured) {
        cudaFuncSetAttribute(vq_mma_argmax_kernel,
                             cudaFuncAttributeMaxDynamicSharedMemorySize, SMEM_TOTAL);
        configured = 1;
    }

    vq_prep_kernel<<<(NK * ND) / 256, 256>>>(emb);
    vq_mma_argmax_kernel<<<NTOK / 256, 256, SMEM_TOTAL>>>(in, emb, embu, out);
    vq_finalize_kernel<<<1, 256>>>(out);
}